// round 4
// baseline (speedup 1.0000x reference)
#include <cuda_runtime.h>
#include <cuda_bf16.h>
#include <cstdint>

#define EPS_ 1e-3f
#define B_   2
#define H_   96
#define W_   96
#define C_   64
#define CQ   8
#define HW_  9216
#define BHW  (B_*HW_)
#define NMT  72            // number of 128-wide tiles along m / n

// ---------------- scratch (static device arrays; no allocation) ----------------
__device__ float          g_q[BHW * CQ];                // Q rows, fp32 [n][8]
__device__ float          g_k[BHW * CQ];                // K rows, fp32 [m][8]
__device__ float          g_v[BHW * C_];                // V rows, fp32 [n][c]
__device__ __nv_bfloat16  g_vsT[(size_t)B_ * C_ * HW_]; // Vs^T [b][c][n], bf16
__device__ float          g_rsum[BHW];                  // softmax denominators

// ---------------- helpers ----------------
__device__ __forceinline__ unsigned f2tf32(float f) {
    unsigned r;
    asm("cvt.rna.tf32.f32 %0, %1;" : "=r"(r) : "f"(f));
    return r;
}
__device__ __forceinline__ unsigned packbf2(float hi, float lo) {
    unsigned r;
    asm("cvt.rn.bf16x2.f32 %0, %1, %2;" : "=r"(r) : "f"(hi), "f"(lo));
    return r;
}
__device__ __forceinline__ void mma_tf32(float* d, const unsigned* a, unsigned b0, unsigned b1) {
    asm volatile(
        "mma.sync.aligned.m16n8k8.row.col.f32.tf32.tf32.f32 "
        "{%0,%1,%2,%3}, {%4,%5,%6,%7}, {%8,%9}, {%0,%1,%2,%3};\n"
        : "+f"(d[0]), "+f"(d[1]), "+f"(d[2]), "+f"(d[3])
        : "r"(a[0]), "r"(a[1]), "r"(a[2]), "r"(a[3]), "r"(b0), "r"(b1));
}
__device__ __forceinline__ void mma_bf16(float* d, const unsigned* a, unsigned b0, unsigned b1) {
    asm volatile(
        "mma.sync.aligned.m16n8k16.row.col.f32.bf16.bf16.f32 "
        "{%0,%1,%2,%3}, {%4,%5,%6,%7}, {%8,%9}, {%0,%1,%2,%3};\n"
        : "+f"(d[0]), "+f"(d[1]), "+f"(d[2]), "+f"(d[3])
        : "r"(a[0]), "r"(a[1]), "r"(a[2]), "r"(a[3]), "r"(b0), "r"(b1));
}
__device__ __forceinline__ void ldsm4(unsigned* r, const void* p) {
    unsigned a = (unsigned)__cvta_generic_to_shared(p);
    asm volatile("ldmatrix.sync.aligned.m8n8.x4.shared.b16 {%0,%1,%2,%3}, [%4];"
                 : "=r"(r[0]), "=r"(r[1]), "=r"(r[2]), "=r"(r[3]) : "r"(a));
}
__device__ __forceinline__ void cpa16(void* dst, const void* src) {
    unsigned d = (unsigned)__cvta_generic_to_shared(dst);
    asm volatile("cp.async.cg.shared.global [%0], [%1], 16;" :: "r"(d), "l"(src));
}
__device__ __forceinline__ void cpa_commit() { asm volatile("cp.async.commit_group;"); }
template <int N>
__device__ __forceinline__ void cpa_wait() { asm volatile("cp.async.wait_group %0;" :: "n"(N)); }

// ---------------- kernel 1: fused convs + BN + ReLU (4 pixels / block) ----------------
__global__ __launch_bounds__(256) void prep_kernel(const float* __restrict__ x,
    const float* __restrict__ Wq, const float* __restrict__ bq,
    const float* __restrict__ gq, const float* __restrict__ betaq,
    const float* __restrict__ mq, const float* __restrict__ vq,
    const float* __restrict__ Wk, const float* __restrict__ bk,
    const float* __restrict__ gk, const float* __restrict__ betak,
    const float* __restrict__ mk, const float* __restrict__ vk,
    const float* __restrict__ Wv, const float* __restrict__ bv)
{
    __shared__ float xc[6][C_];   // center row, cols w0-1 .. w0+4
    __shared__ float xu[4][C_];   // up row, cols w0..w0+3
    __shared__ float xd[4][C_];   // down row
    int pix0 = blockIdx.x * 4;
    int b = pix0 / HW_;
    int n0 = pix0 - b * HW_;
    int h = n0 / W_, w0 = n0 - h * W_;   // w0 multiple of 4, row never straddles
    int t = threadIdx.x;
    const float* xb = x + (size_t)b * HW_ * C_;

    for (int i = t; i < 6 * C_; i += 256) {
        int j = i >> 6, c = i & 63, wi = w0 - 1 + j;
        xc[j][c] = (wi >= 0 && wi < W_) ? xb[(h * W_ + wi) * C_ + c] : 0.f;
    }
    for (int i = t; i < 4 * C_; i += 256) {
        int j = i >> 6, c = i & 63;
        xu[j][c] = (h > 0)      ? xb[((h - 1) * W_ + w0 + j) * C_ + c] : 0.f;
        xd[j][c] = (h < H_ - 1) ? xb[((h + 1) * W_ + w0 + j) * C_ + c] : 0.f;
    }
    __syncthreads();

    int px = t >> 6, c = t & 63;
    int pix = pix0 + px;

    float acc = bv[c];
    #pragma unroll 8
    for (int ci = 0; ci < C_; ci++)
        acc = fmaf(xc[px + 1][ci], Wv[ci * C_ + c], acc);
    g_v[(size_t)pix * C_ + c] = acc;

    if (c < CQ) {
        float s = 0.f;
        #pragma unroll 8
        for (int ci = 0; ci < C_; ci++) {
            s = fmaf(xc[px    ][ci], Wq[(0 * C_ + ci) * CQ + c], s);
            s = fmaf(xc[px + 1][ci], Wq[(1 * C_ + ci) * CQ + c], s);
            s = fmaf(xc[px + 2][ci], Wq[(2 * C_ + ci) * CQ + c], s);
        }
        float sc  = gq[c] * rsqrtf(vq[c] + EPS_);
        float val = fmaf(s + bq[c] - mq[c], sc, betaq[c]);
        g_q[pix * CQ + c] = fmaxf(val, 0.f);
    } else if (c < 2 * CQ) {
        int cc = c - CQ;
        float s = 0.f;
        #pragma unroll 8
        for (int ci = 0; ci < C_; ci++) {
            s = fmaf(xu[px    ][ci], Wk[(0 * C_ + ci) * CQ + cc], s);
            s = fmaf(xc[px + 1][ci], Wk[(1 * C_ + ci) * CQ + cc], s);
            s = fmaf(xd[px    ][ci], Wk[(2 * C_ + ci) * CQ + cc], s);
        }
        float sc  = gk[cc] * rsqrtf(vk[cc] + EPS_);
        float val = fmaf(s + bk[cc] - mk[cc], sc, betak[cc]);
        g_k[pix * CQ + cc] = fmaxf(val, 0.f);
    }
}

// ---------------- kernel 2: softmax denominators (no P store) ----------------
// block owns 128 n-rows (blockIdx.x), sweeps all m; warp w owns n-slice [16w,16w+16)
__global__ __launch_bounds__(256) void stats_kernel()
{
    int b  = blockIdx.y;
    int n0 = blockIdx.x * 128;
    int t = threadIdx.x, lane = t & 31, w = t >> 5;
    int g = lane >> 2, tq = lane & 3;
    size_t bHW = (size_t)b * HW_;

    unsigned bq[4];
    {
        const float* qp = &g_q[(bHW + n0 + 16 * w + g) * 8];
        bq[0] = f2tf32(qp[tq]);
        bq[1] = f2tf32(qp[tq + 4]);
        bq[2] = f2tf32(qp[64 + tq]);
        bq[3] = f2tf32(qp[64 + tq + 4]);
    }

    float cs0 = 0.f, cs1 = 0.f, cs2 = 0.f, cs3 = 0.f;
    const float* kb = &g_k[bHW * 8];

    for (int mt = 0; mt < NMT; mt++) {
        #pragma unroll
        for (int i = 0; i < 8; i++) {
            int m = mt * 128 + 16 * i;
            unsigned a[4];
            a[0] = f2tf32(kb[(m + g    ) * 8 + tq    ]);
            a[1] = f2tf32(kb[(m + g + 8) * 8 + tq    ]);
            a[2] = f2tf32(kb[(m + g    ) * 8 + tq + 4]);
            a[3] = f2tf32(kb[(m + g + 8) * 8 + tq + 4]);
            float d[4] = {0.f, 0.f, 0.f, 0.f};
            float e[4] = {0.f, 0.f, 0.f, 0.f};
            mma_tf32(d, a, bq[0], bq[1]);
            mma_tf32(e, a, bq[2], bq[3]);
            cs0 += __expf(d[0]) + __expf(d[2]);
            cs1 += __expf(d[1]) + __expf(d[3]);
            cs2 += __expf(e[0]) + __expf(e[2]);
            cs3 += __expf(e[1]) + __expf(e[3]);
        }
    }

    #pragma unroll
    for (int s = 16; s >= 4; s >>= 1) {
        cs0 += __shfl_xor_sync(0xffffffffu, cs0, s);
        cs1 += __shfl_xor_sync(0xffffffffu, cs1, s);
        cs2 += __shfl_xor_sync(0xffffffffu, cs2, s);
        cs3 += __shfl_xor_sync(0xffffffffu, cs3, s);
    }
    if (lane < 4) {
        float* rp = &g_rsum[bHW + n0 + 16 * w];
        rp[2 * tq]     = cs0;
        rp[2 * tq + 1] = cs1;
        rp[2 * tq + 8] = cs2;
        rp[2 * tq + 9] = cs3;
    }
}

// ---------------- kernel 3: Vs^T = bf16(gamma * v / rowsum), [b][c][n] ----------------
__global__ void scalev_kernel(const float* __restrict__ gamma)
{
    size_t o = (size_t)blockIdx.x * 256 + threadIdx.x;  // over B*C*HW, n fastest
    int n = (int)(o % HW_);
    int c = (int)((o / HW_) % C_);
    int b = (int)(o / ((size_t)HW_ * C_));
    float val = g_v[((size_t)(b * HW_ + n)) * C_ + c] * gamma[0] / g_rsum[b * HW_ + n];
    g_vsT[o] = __float2bfloat16(val);
}

// ---------------- kernel 4: fused P-recompute + bf16 GEMM + residual ----------------
// block = 128 m x 64 c output; n chunks of 128, P recomputed in smem (double-buffered)
#define KS_OFF   0
#define PS_OFF   6144
#define VS_OFF   (6144 + 69632)
#define SMEM_TOT (VS_OFF + 34816)

__global__ __launch_bounds__(256)
void fused_kernel(const float* __restrict__ x, float* __restrict__ out)
{
    extern __shared__ __align__(16) char smem_raw[];
    float*         ks  = (float*)(smem_raw + KS_OFF);                 // [128][12]
    __nv_bfloat16* PsB = (__nv_bfloat16*)(smem_raw + PS_OFF);         // [2][128][136]
    __nv_bfloat16* VsB = (__nv_bfloat16*)(smem_raw + VS_OFF);         // [2][64][136]
#define PS(bf, r, c) PsB[(bf) * (128 * 136) + (r) * 136 + (c)]
#define VS(bf, r, c) VsB[(bf) * (64 * 136) + (r) * 136 + (c)]

    int b   = blockIdx.y;
    int bm0 = blockIdx.x * 128;
    int t = threadIdx.x, lane = t & 31, w = t >> 5;
    int g = lane >> 2, tq = lane & 3;
    int wc = w & 3;        // c quarter (16)
    int wm = w >> 2;       // m half (64)
    size_t bHW = (size_t)b * HW_;
    const __nv_bfloat16* Ag = &g_vsT[(size_t)b * C_ * HW_];

    // stage K tile for this block's 128 m rows (fixed all kernel)
    for (int i = t; i < 1024; i += 256)
        ks[(i >> 3) * 12 + (i & 7)] = g_k[(bHW + bm0) * 8 + i];

    // prefetch Vs chunk 0
    {
        #pragma unroll
        for (int j = 0; j < 4; j++) {
            int idx = t + j * 256, row = idx >> 4, seg = idx & 15;
            cpa16(&VS(0, row, seg * 8), Ag + (size_t)row * HW_ + seg * 8);
        }
        cpa_commit();
    }

    float acc[8][4];
    #pragma unroll
    for (int i = 0; i < 8; i++)
        #pragma unroll
        for (int j = 0; j < 4; j++) acc[i][j] = 0.f;

    // Q frags for chunk 0
    unsigned bqf[4];
    {
        const float* qp = &g_q[(bHW + 16 * w + g) * 8];
        bqf[0] = f2tf32(qp[tq]);     bqf[1] = f2tf32(qp[tq + 4]);
        bqf[2] = f2tf32(qp[64 + tq]); bqf[3] = f2tf32(qp[64 + tq + 4]);
    }
    cpa_wait<0>();
    __syncthreads();

    int c0 = 16 * w + 2 * tq;
    // produce Ps[0] for chunk 0
    #pragma unroll
    for (int i = 0; i < 8; i++) {
        unsigned a[4];
        a[0] = f2tf32(ks[(16 * i + g    ) * 12 + tq    ]);
        a[1] = f2tf32(ks[(16 * i + g + 8) * 12 + tq    ]);
        a[2] = f2tf32(ks[(16 * i + g    ) * 12 + tq + 4]);
        a[3] = f2tf32(ks[(16 * i + g + 8) * 12 + tq + 4]);
        float d[4] = {0.f, 0.f, 0.f, 0.f};
        float e[4] = {0.f, 0.f, 0.f, 0.f};
        mma_tf32(d, a, bqf[0], bqf[1]);
        mma_tf32(e, a, bqf[2], bqf[3]);
        *(unsigned*)&PS(0, 16 * i + g,     c0    ) = packbf2(__expf(d[1]), __expf(d[0]));
        *(unsigned*)&PS(0, 16 * i + g + 8, c0    ) = packbf2(__expf(d[3]), __expf(d[2]));
        *(unsigned*)&PS(0, 16 * i + g,     c0 + 8) = packbf2(__expf(e[1]), __expf(e[0]));
        *(unsigned*)&PS(0, 16 * i + g + 8, c0 + 8) = packbf2(__expf(e[3]), __expf(e[2]));
    }
    __syncthreads();

    for (int ck = 0; ck < NMT; ck++) {
        int buf = ck & 1;
        bool more = (ck + 1 < NMT);
        if (more) {
            int n1 = (ck + 1) * 128;
            #pragma unroll
            for (int j = 0; j < 4; j++) {
                int idx = t + j * 256, row = idx >> 4, seg = idx & 15;
                cpa16(&VS(buf ^ 1, row, seg * 8), Ag + (size_t)row * HW_ + n1 + seg * 8);
            }
            cpa_commit();
            const float* qp = &g_q[(bHW + n1 + 16 * w + g) * 8];
            bqf[0] = f2tf32(qp[tq]);      bqf[1] = f2tf32(qp[tq + 4]);
            bqf[2] = f2tf32(qp[64 + tq]); bqf[3] = f2tf32(qp[64 + tq + 4]);
        }

        #pragma unroll
        for (int i = 0; i < 8; i++) {
            // produce subtile i of Ps[buf^1] (chunk ck+1)
            if (more) {
                unsigned a[4];
                a[0] = f2tf32(ks[(16 * i + g    ) * 12 + tq    ]);
                a[1] = f2tf32(ks[(16 * i + g + 8) * 12 + tq    ]);
                a[2] = f2tf32(ks[(16 * i + g    ) * 12 + tq + 4]);
                a[3] = f2tf32(ks[(16 * i + g + 8) * 12 + tq + 4]);
                float d[4] = {0.f, 0.f, 0.f, 0.f};
                float e[4] = {0.f, 0.f, 0.f, 0.f};
                mma_tf32(d, a, bqf[0], bqf[1]);
                mma_tf32(e, a, bqf[2], bqf[3]);
                *(unsigned*)&PS(buf ^ 1, 16 * i + g,     c0    ) = packbf2(__expf(d[1]), __expf(d[0]));
                *(unsigned*)&PS(buf ^ 1, 16 * i + g + 8, c0    ) = packbf2(__expf(d[3]), __expf(d[2]));
                *(unsigned*)&PS(buf ^ 1, 16 * i + g,     c0 + 8) = packbf2(__expf(e[1]), __expf(e[0]));
                *(unsigned*)&PS(buf ^ 1, 16 * i + g + 8, c0 + 8) = packbf2(__expf(e[3]), __expf(e[2]));
            }
            // GEMM k-step i on chunk ck
            {
                int k0 = i * 16;
                unsigned af[4];
                ldsm4(af, &VS(buf, 16 * wc + (lane & 7) + ((lane >> 3) & 1) * 8,
                              (lane >> 4) * 8 + k0));
                #pragma unroll
                for (int p = 0; p < 4; p++) {
                    unsigned bb[4];
                    ldsm4(bb, &PS(buf, 64 * wm + 16 * p + (lane & 7) + ((lane >> 4) & 1) * 8,
                                  k0 + ((lane >> 3) & 1) * 8));
                    mma_bf16(acc[2 * p    ], af, bb[0], bb[1]);
                    mma_bf16(acc[2 * p + 1], af, bb[2], bb[3]);
                }
            }
        }
        cpa_wait<0>();
        __syncthreads();
    }

    // epilogue: out[b][m][c] = D[c][m] + x[b][m][c]
    int cc0 = 16 * wc + g;
    #pragma unroll
    for (int jo = 0; jo < 8; jo++) {
        int m = bm0 + 64 * wm + 8 * jo + 2 * tq;
        size_t i00 = (bHW + m) * (size_t)C_ + cc0;
        out[i00]          = acc[jo][0] + x[i00];
        out[i00 + C_]     = acc[jo][1] + x[i00 + C_];
        out[i00 + 8]      = acc[jo][2] + x[i00 + 8];
        out[i00 + C_ + 8] = acc[jo][3] + x[i00 + C_ + 8];
    }
#undef PS
#undef VS
}

// ---------------- launch ----------------
extern "C" void kernel_launch(void* const* d_in, const int* in_sizes, int n_in,
                              void* d_out, int out_size)
{
    const float* x     = (const float*)d_in[0];
    const float* Wq    = (const float*)d_in[1];
    const float* bq    = (const float*)d_in[2];
    const float* gq    = (const float*)d_in[3];
    const float* betaq = (const float*)d_in[4];
    const float* mq    = (const float*)d_in[5];
    const float* vq    = (const float*)d_in[6];
    const float* Wk    = (const float*)d_in[7];
    const float* bk    = (const float*)d_in[8];
    const float* gk    = (const float*)d_in[9];
    const float* betak = (const float*)d_in[10];
    const float* mk    = (const float*)d_in[11];
    const float* vk    = (const float*)d_in[12];
    const float* Wv    = (const float*)d_in[13];
    const float* bv    = (const float*)d_in[14];
    const float* gamma = (const float*)d_in[15];
    float* out = (float*)d_out;

    // unconditional, idempotent; host-side attribute set (not a stream op)
    cudaFuncSetAttribute(fused_kernel, cudaFuncAttributeMaxDynamicSharedMemorySize, SMEM_TOT);

    prep_kernel<<<BHW / 4, 256>>>(x, Wq, bq, gq, betaq, mq, vq,
                                  Wk, bk, gk, betak, mk, vk, Wv, bv);
    stats_kernel<<<dim3(NMT, B_), 256>>>();
    scalev_kernel<<<(unsigned)(((size_t)B_ * C_ * HW_) / 256), 256>>>(gamma);
    fused_kernel<<<dim3(NMT, B_), 256, SMEM_TOT>>>(x, out);
}

// round 5
// speedup vs baseline: 1.4883x; 1.4883x over previous
#include <cuda_runtime.h>
#include <cuda_bf16.h>
#include <cstdint>

#define EPS_ 1e-3f
#define B_   2
#define H_   96
#define W_   96
#define C_   64
#define CQ   8
#define HW_  9216
#define BHW  (B_*HW_)
#define NMT  72            // number of 128-wide tiles along m / n
#define MZ_  4             // m-splits in stats
#define MCH  (NMT / MZ_)   // 18 chunks of 128 m per stats block

// ---------------- scratch (static device arrays; no allocation) ----------------
__device__ float          g_q[BHW * CQ];                // Q rows, fp32 [n][8]
__device__ float          g_k[BHW * CQ];                // K rows, fp32 [m][8]
__device__ float          g_v[BHW * C_];                // V rows, fp32 [n][c]
__device__ __nv_bfloat16  g_vsT[(size_t)B_ * C_ * HW_]; // Vs^T [b][c][n], bf16
__device__ float          g_part[B_ * MZ_ * HW_];       // stats partials [b][mz][n]
__device__ float          g_rsum[BHW];                  // softmax denominators

// ---------------- helpers ----------------
__device__ __forceinline__ unsigned f2tf32(float f) {
    unsigned r;
    asm("cvt.rna.tf32.f32 %0, %1;" : "=r"(r) : "f"(f));
    return r;
}
__device__ __forceinline__ unsigned packbf2(float hi, float lo) {
    unsigned r;
    asm("cvt.rn.bf16x2.f32 %0, %1, %2;" : "=r"(r) : "f"(hi), "f"(lo));
    return r;
}
__device__ __forceinline__ void mma_tf32(float* d, const unsigned* a, unsigned b0, unsigned b1) {
    asm volatile(
        "mma.sync.aligned.m16n8k8.row.col.f32.tf32.tf32.f32 "
        "{%0,%1,%2,%3}, {%4,%5,%6,%7}, {%8,%9}, {%0,%1,%2,%3};\n"
        : "+f"(d[0]), "+f"(d[1]), "+f"(d[2]), "+f"(d[3])
        : "r"(a[0]), "r"(a[1]), "r"(a[2]), "r"(a[3]), "r"(b0), "r"(b1));
}
__device__ __forceinline__ void mma_bf16(float* d, const unsigned* a, unsigned b0, unsigned b1) {
    asm volatile(
        "mma.sync.aligned.m16n8k16.row.col.f32.bf16.bf16.f32 "
        "{%0,%1,%2,%3}, {%4,%5,%6,%7}, {%8,%9}, {%0,%1,%2,%3};\n"
        : "+f"(d[0]), "+f"(d[1]), "+f"(d[2]), "+f"(d[3])
        : "r"(a[0]), "r"(a[1]), "r"(a[2]), "r"(a[3]), "r"(b0), "r"(b1));
}
__device__ __forceinline__ void ldsm4(unsigned* r, const void* p) {
    unsigned a = (unsigned)__cvta_generic_to_shared(p);
    asm volatile("ldmatrix.sync.aligned.m8n8.x4.shared.b16 {%0,%1,%2,%3}, [%4];"
                 : "=r"(r[0]), "=r"(r[1]), "=r"(r[2]), "=r"(r[3]) : "r"(a));
}
__device__ __forceinline__ void cpa16(void* dst, const void* src) {
    unsigned d = (unsigned)__cvta_generic_to_shared(dst);
    asm volatile("cp.async.cg.shared.global [%0], [%1], 16;" :: "r"(d), "l"(src));
}
__device__ __forceinline__ void cpa_commit() { asm volatile("cp.async.commit_group;"); }
template <int N>
__device__ __forceinline__ void cpa_wait() { asm volatile("cp.async.wait_group %0;" :: "n"(N)); }

// ---------------- kernel 1: fused convs + BN + ReLU (4 pixels / block) ----------------
__global__ __launch_bounds__(256) void prep_kernel(const float* __restrict__ x,
    const float* __restrict__ Wq, const float* __restrict__ bq,
    const float* __restrict__ gq, const float* __restrict__ betaq,
    const float* __restrict__ mq, const float* __restrict__ vq,
    const float* __restrict__ Wk, const float* __restrict__ bk,
    const float* __restrict__ gk, const float* __restrict__ betak,
    const float* __restrict__ mk, const float* __restrict__ vk,
    const float* __restrict__ Wv, const float* __restrict__ bv)
{
    __shared__ float xc[6][C_];
    __shared__ float xu[4][C_];
    __shared__ float xd[4][C_];
    int pix0 = blockIdx.x * 4;
    int b = pix0 / HW_;
    int n0 = pix0 - b * HW_;
    int h = n0 / W_, w0 = n0 - h * W_;
    int t = threadIdx.x;
    const float* xb = x + (size_t)b * HW_ * C_;

    for (int i = t; i < 6 * C_; i += 256) {
        int j = i >> 6, c = i & 63, wi = w0 - 1 + j;
        xc[j][c] = (wi >= 0 && wi < W_) ? xb[(h * W_ + wi) * C_ + c] : 0.f;
    }
    for (int i = t; i < 4 * C_; i += 256) {
        int j = i >> 6, c = i & 63;
        xu[j][c] = (h > 0)      ? xb[((h - 1) * W_ + w0 + j) * C_ + c] : 0.f;
        xd[j][c] = (h < H_ - 1) ? xb[((h + 1) * W_ + w0 + j) * C_ + c] : 0.f;
    }
    __syncthreads();

    int px = t >> 6, c = t & 63;
    int pix = pix0 + px;

    float acc = bv[c];
    #pragma unroll 8
    for (int ci = 0; ci < C_; ci++)
        acc = fmaf(xc[px + 1][ci], Wv[ci * C_ + c], acc);
    g_v[(size_t)pix * C_ + c] = acc;

    if (c < CQ) {
        float s = 0.f;
        #pragma unroll 8
        for (int ci = 0; ci < C_; ci++) {
            s = fmaf(xc[px    ][ci], Wq[(0 * C_ + ci) * CQ + c], s);
            s = fmaf(xc[px + 1][ci], Wq[(1 * C_ + ci) * CQ + c], s);
            s = fmaf(xc[px + 2][ci], Wq[(2 * C_ + ci) * CQ + c], s);
        }
        float sc  = gq[c] * rsqrtf(vq[c] + EPS_);
        float val = fmaf(s + bq[c] - mq[c], sc, betaq[c]);
        g_q[pix * CQ + c] = fmaxf(val, 0.f);
    } else if (c < 2 * CQ) {
        int cc = c - CQ;
        float s = 0.f;
        #pragma unroll 8
        for (int ci = 0; ci < C_; ci++) {
            s = fmaf(xu[px    ][ci], Wk[(0 * C_ + ci) * CQ + cc], s);
            s = fmaf(xc[px + 1][ci], Wk[(1 * C_ + ci) * CQ + cc], s);
            s = fmaf(xd[px    ][ci], Wk[(2 * C_ + ci) * CQ + cc], s);
        }
        float sc  = gk[cc] * rsqrtf(vk[cc] + EPS_);
        float val = fmaf(s + bk[cc] - mk[cc], sc, betak[cc]);
        g_k[pix * CQ + cc] = fmaxf(val, 0.f);
    }
}

// ---------------- kernel 2: softmax-denominator partials ----------------
// grid (72, B, MZ_): block owns 128 n-rows, sweeps 1/MZ_ of m via smem-staged K chunks
__global__ __launch_bounds__(256) void stats_kernel()
{
    __shared__ float ks[2][128][12];   // K chunk, padded to 12 (conflict-free frag reads)
    int b  = blockIdx.y;
    int n0 = blockIdx.x * 128;
    int mz = blockIdx.z;
    int m_base = mz * (HW_ / MZ_);
    int t = threadIdx.x, lane = t & 31, w = t >> 5;
    int g = lane >> 2, tq = lane & 3;
    size_t bHW = (size_t)b * HW_;
    const float* kb = &g_k[bHW * 8];

    unsigned bq[4];
    {
        const float* qp = &g_q[(bHW + n0 + 16 * w + g) * 8];
        bq[0] = f2tf32(qp[tq]);
        bq[1] = f2tf32(qp[tq + 4]);
        bq[2] = f2tf32(qp[64 + tq]);
        bq[3] = f2tf32(qp[64 + tq + 4]);
    }

    // prefetch chunk 0: 128 rows x 8 floats, 256 x 16B
    {
        int row = t >> 1, seg = t & 1;
        cpa16(&ks[0][row][seg * 4], kb + (m_base + row) * 8 + seg * 4);
        cpa_commit();
    }

    float cs0 = 0.f, cs1 = 0.f, cs2 = 0.f, cs3 = 0.f;

    for (int ch = 0; ch < MCH; ch++) {
        int buf = ch & 1;
        if (ch + 1 < MCH) {
            int row = t >> 1, seg = t & 1;
            cpa16(&ks[buf ^ 1][row][seg * 4], kb + (m_base + (ch + 1) * 128 + row) * 8 + seg * 4);
            cpa_commit();
            cpa_wait<1>();
        } else {
            cpa_wait<0>();
        }
        __syncthreads();

        #pragma unroll
        for (int i = 0; i < 8; i++) {
            unsigned a[4];
            a[0] = f2tf32(ks[buf][16 * i + g    ][tq    ]);
            a[1] = f2tf32(ks[buf][16 * i + g + 8][tq    ]);
            a[2] = f2tf32(ks[buf][16 * i + g    ][tq + 4]);
            a[3] = f2tf32(ks[buf][16 * i + g + 8][tq + 4]);
            float d[4] = {0.f, 0.f, 0.f, 0.f};
            float e[4] = {0.f, 0.f, 0.f, 0.f};
            mma_tf32(d, a, bq[0], bq[1]);
            mma_tf32(e, a, bq[2], bq[3]);
            cs0 += __expf(d[0]) + __expf(d[2]);
            cs1 += __expf(d[1]) + __expf(d[3]);
            cs2 += __expf(e[0]) + __expf(e[2]);
            cs3 += __expf(e[1]) + __expf(e[3]);
        }
        __syncthreads();
    }

    #pragma unroll
    for (int s = 16; s >= 4; s >>= 1) {
        cs0 += __shfl_xor_sync(0xffffffffu, cs0, s);
        cs1 += __shfl_xor_sync(0xffffffffu, cs1, s);
        cs2 += __shfl_xor_sync(0xffffffffu, cs2, s);
        cs3 += __shfl_xor_sync(0xffffffffu, cs3, s);
    }
    if (lane < 4) {
        float* rp = &g_part[((b * MZ_) + mz) * HW_ + n0 + 16 * w];
        rp[2 * tq]     = cs0;
        rp[2 * tq + 1] = cs1;
        rp[2 * tq + 8] = cs2;
        rp[2 * tq + 9] = cs3;
    }
}

// ---------------- kernel 2b: reduce partials -> rowsum ----------------
__global__ void rsum_kernel()
{
    int i = blockIdx.x * 256 + threadIdx.x;   // over BHW
    int b = i / HW_, n = i - b * HW_;
    float s = 0.f;
    #pragma unroll
    for (int mz = 0; mz < MZ_; mz++)
        s += g_part[((b * MZ_) + mz) * HW_ + n];
    g_rsum[i] = s;
}

// ---------------- kernel 3: Vs^T = bf16(gamma * v / rowsum), [b][c][n] ----------------
__global__ void scalev_kernel(const float* __restrict__ gamma)
{
    size_t o = (size_t)blockIdx.x * 256 + threadIdx.x;  // over B*C*HW, n fastest
    int n = (int)(o % HW_);
    int c = (int)((o / HW_) % C_);
    int b = (int)(o / ((size_t)HW_ * C_));
    float val = g_v[((size_t)(b * HW_ + n)) * C_ + c] * gamma[0] / g_rsum[b * HW_ + n];
    g_vsT[o] = __float2bfloat16(val);
}

// ---------------- kernel 4: fused P-recompute + bf16 GEMM + residual (512 thr) ----------------
#define PS_OFF   0
#define VS_OFF   69632
#define SMEM_TOT (VS_OFF + 34816)   // 104448 bytes

__global__ __launch_bounds__(512)
void fused_kernel(const float* __restrict__ x, float* __restrict__ out)
{
    extern __shared__ __align__(16) char smem_raw[];
    __nv_bfloat16* PsB = (__nv_bfloat16*)(smem_raw + PS_OFF);   // [2][128][136]
    __nv_bfloat16* VsB = (__nv_bfloat16*)(smem_raw + VS_OFF);   // [2][64][136]
#define PS(bf, r, c) PsB[(bf) * (128 * 136) + (r) * 136 + (c)]
#define VS(bf, r, c) VsB[(bf) * (64 * 136) + (r) * 136 + (c)]

    int b   = blockIdx.y;
    int bm0 = blockIdx.x * 128;
    int t = threadIdx.x, lane = t & 31, w = t >> 5;     // 16 warps
    int g = lane >> 2, tq = lane & 3;
    int wc = w & 3;        // c quarter (16 rows)
    int wm = w >> 2;       // m quarter (32 cols)
    size_t bHW = (size_t)b * HW_;
    const float* kb = &g_k[bHW * 8];
    const __nv_bfloat16* Ag = &g_vsT[(size_t)b * C_ * HW_];

    // preload K A-fragments for this block's 128 m rows into registers (fixed all kernel)
    unsigned ka[8][4];
    #pragma unroll
    for (int i = 0; i < 8; i++) {
        ka[i][0] = f2tf32(kb[(bm0 + 16 * i + g    ) * 8 + tq    ]);
        ka[i][1] = f2tf32(kb[(bm0 + 16 * i + g + 8) * 8 + tq    ]);
        ka[i][2] = f2tf32(kb[(bm0 + 16 * i + g    ) * 8 + tq + 4]);
        ka[i][3] = f2tf32(kb[(bm0 + 16 * i + g + 8) * 8 + tq + 4]);
    }

    // prefetch Vs chunk 0 (64 rows x 128 cols bf16 = 1024 x 16B)
    {
        #pragma unroll
        for (int j = 0; j < 2; j++) {
            int idx = t + j * 512, row = idx >> 4, seg = idx & 15;
            cpa16(&VS(0, row, seg * 8), Ag + (size_t)row * HW_ + seg * 8);
        }
        cpa_commit();
    }

    float acc[4][4];
    #pragma unroll
    for (int i = 0; i < 4; i++)
        #pragma unroll
        for (int j = 0; j < 4; j++) acc[i][j] = 0.f;

    // Q B-fragments for chunk 0 (warp owns n-slice [8w, 8w+8))
    unsigned bq0, bq1;
    {
        const float* qp = &g_q[(bHW + 8 * w + g) * 8];
        bq0 = f2tf32(qp[tq]);
        bq1 = f2tf32(qp[tq + 4]);
    }
    cpa_wait<0>();
    __syncthreads();

    int c0 = 8 * w + 2 * tq;
    // produce Ps[0] for chunk 0
    #pragma unroll
    for (int i = 0; i < 8; i++) {
        float d[4] = {0.f, 0.f, 0.f, 0.f};
        mma_tf32(d, ka[i], bq0, bq1);
        *(unsigned*)&PS(0, 16 * i + g,     c0) = packbf2(__expf(d[1]), __expf(d[0]));
        *(unsigned*)&PS(0, 16 * i + g + 8, c0) = packbf2(__expf(d[3]), __expf(d[2]));
    }
    __syncthreads();

    for (int ck = 0; ck < NMT; ck++) {
        int buf = ck & 1;
        bool more = (ck + 1 < NMT);
        unsigned bq0n = 0, bq1n = 0;
        if (more) {
            int n1 = (ck + 1) * 128;
            #pragma unroll
            for (int j = 0; j < 2; j++) {
                int idx = t + j * 512, row = idx >> 4, seg = idx & 15;
                cpa16(&VS(buf ^ 1, row, seg * 8), Ag + (size_t)row * HW_ + n1 + seg * 8);
            }
            cpa_commit();
            const float* qp = &g_q[(bHW + n1 + 8 * w + g) * 8];
            bq0n = f2tf32(qp[tq]);
            bq1n = f2tf32(qp[tq + 4]);
        }

        #pragma unroll
        for (int i = 0; i < 8; i++) {
            // produce subtile i of chunk ck+1 into PS[buf^1]
            if (more) {
                float d[4] = {0.f, 0.f, 0.f, 0.f};
                mma_tf32(d, ka[i], bq0n, bq1n);
                *(unsigned*)&PS(buf ^ 1, 16 * i + g,     c0) = packbf2(__expf(d[1]), __expf(d[0]));
                *(unsigned*)&PS(buf ^ 1, 16 * i + g + 8, c0) = packbf2(__expf(d[3]), __expf(d[2]));
            }
            // GEMM k-step i on chunk ck
            {
                int k0 = i * 16;
                unsigned af[4];
                ldsm4(af, &VS(buf, 16 * wc + (lane & 7) + ((lane >> 3) & 1) * 8,
                              (lane >> 4) * 8 + k0));
                #pragma unroll
                for (int p = 0; p < 2; p++) {
                    unsigned bb[4];
                    ldsm4(bb, &PS(buf, 32 * wm + 16 * p + (lane & 7) + ((lane >> 4) & 1) * 8,
                                  k0 + ((lane >> 3) & 1) * 8));
                    mma_bf16(acc[2 * p    ], af, bb[0], bb[1]);
                    mma_bf16(acc[2 * p + 1], af, bb[2], bb[3]);
                }
            }
        }
        cpa_wait<0>();
        __syncthreads();
    }

    // epilogue: out[b][m][c] = D[c][m] + x[b][m][c]
    int cc0 = 16 * wc + g;
    #pragma unroll
    for (int jo = 0; jo < 4; jo++) {
        int m = bm0 + 32 * wm + 8 * jo + 2 * tq;
        size_t i00 = (bHW + m) * (size_t)C_ + cc0;
        out[i00]          = acc[jo][0] + x[i00];
        out[i00 + C_]     = acc[jo][1] + x[i00 + C_];
        out[i00 + 8]      = acc[jo][2] + x[i00 + 8];
        out[i00 + C_ + 8] = acc[jo][3] + x[i00 + C_ + 8];
    }
#undef PS
#undef VS
}

// ---------------- launch ----------------
extern "C" void kernel_launch(void* const* d_in, const int* in_sizes, int n_in,
                              void* d_out, int out_size)
{
    const float* x     = (const float*)d_in[0];
    const float* Wq    = (const float*)d_in[1];
    const float* bq    = (const float*)d_in[2];
    const float* gq    = (const float*)d_in[3];
    const float* betaq = (const float*)d_in[4];
    const float* mq    = (const float*)d_in[5];
    const float* vq    = (const float*)d_in[6];
    const float* Wk    = (const float*)d_in[7];
    const float* bk    = (const float*)d_in[8];
    const float* gk    = (const float*)d_in[9];
    const float* betak = (const float*)d_in[10];
    const float* mk    = (const float*)d_in[11];
    const float* vk    = (const float*)d_in[12];
    const float* Wv    = (const float*)d_in[13];
    const float* bv    = (const float*)d_in[14];
    const float* gamma = (const float*)d_in[15];
    float* out = (float*)d_out;

    // unconditional, idempotent; host-side attribute set (not a stream op)
    cudaFuncSetAttribute(fused_kernel, cudaFuncAttributeMaxDynamicSharedMemorySize, SMEM_TOT);

    prep_kernel<<<BHW / 4, 256>>>(x, Wq, bq, gq, betaq, mq, vq,
                                  Wk, bk, gk, betak, mk, vk, Wv, bv);
    stats_kernel<<<dim3(NMT, B_, MZ_), 256>>>();
    rsum_kernel<<<BHW / 256, 256>>>();
    scalev_kernel<<<(unsigned)(((size_t)B_ * C_ * HW_) / 256), 256>>>(gamma);
    fused_kernel<<<dim3(NMT, B_), 512, SMEM_TOT>>>(x, out);
}

// round 6
// speedup vs baseline: 1.6081x; 1.0805x over previous
#include <cuda_runtime.h>
#include <cuda_bf16.h>
#include <cstdint>

#define EPS_ 1e-3f
#define B_   2
#define H_   96
#define W_   96
#define C_   64
#define CQ   8
#define HW_  9216
#define BHW  (B_*HW_)
#define NMT  72            // number of 128-wide n-chunks
#define MZ_  4             // m-splits in stats
#define MCH  (NMT / MZ_)   // chunks of 128 m per stats block

// ---------------- scratch (static device arrays; no allocation) ----------------
__device__ float          g_q[BHW * CQ];                // Q rows, fp32 [n][8]
__device__ float          g_k[BHW * CQ];                // K rows, fp32 [m][8]
__device__ float          g_v[BHW * C_];                // V rows, fp32 [n][c]
__device__ __nv_bfloat16  g_vsT[(size_t)B_ * C_ * HW_]; // Vs^T [b][c][n], bf16
__device__ float          g_part[B_ * MZ_ * HW_];       // stats partials [b][mz][n]
__device__ float          g_rsum[BHW];                  // softmax denominators

// ---------------- helpers ----------------
__device__ __forceinline__ unsigned f2tf32(float f) {
    unsigned r;
    asm("cvt.rna.tf32.f32 %0, %1;" : "=r"(r) : "f"(f));
    return r;
}
__device__ __forceinline__ unsigned packbf2(float hi, float lo) {
    unsigned r;
    asm("cvt.rn.bf16x2.f32 %0, %1, %2;" : "=r"(r) : "f"(hi), "f"(lo));
    return r;
}
__device__ __forceinline__ void mma_tf32(float* d, const unsigned* a, unsigned b0, unsigned b1) {
    asm volatile(
        "mma.sync.aligned.m16n8k8.row.col.f32.tf32.tf32.f32 "
        "{%0,%1,%2,%3}, {%4,%5,%6,%7}, {%8,%9}, {%0,%1,%2,%3};\n"
        : "+f"(d[0]), "+f"(d[1]), "+f"(d[2]), "+f"(d[3])
        : "r"(a[0]), "r"(a[1]), "r"(a[2]), "r"(a[3]), "r"(b0), "r"(b1));
}
__device__ __forceinline__ void mma_bf16(float* d, const unsigned* a, unsigned b0, unsigned b1) {
    asm volatile(
        "mma.sync.aligned.m16n8k16.row.col.f32.bf16.bf16.f32 "
        "{%0,%1,%2,%3}, {%4,%5,%6,%7}, {%8,%9}, {%0,%1,%2,%3};\n"
        : "+f"(d[0]), "+f"(d[1]), "+f"(d[2]), "+f"(d[3])
        : "r"(a[0]), "r"(a[1]), "r"(a[2]), "r"(a[3]), "r"(b0), "r"(b1));
}
__device__ __forceinline__ void ldsm4(unsigned* r, const void* p) {
    unsigned a = (unsigned)__cvta_generic_to_shared(p);
    asm volatile("ldmatrix.sync.aligned.m8n8.x4.shared.b16 {%0,%1,%2,%3}, [%4];"
                 : "=r"(r[0]), "=r"(r[1]), "=r"(r[2]), "=r"(r[3]) : "r"(a));
}
__device__ __forceinline__ void cpa16(void* dst, const void* src) {
    unsigned d = (unsigned)__cvta_generic_to_shared(dst);
    asm volatile("cp.async.cg.shared.global [%0], [%1], 16;" :: "r"(d), "l"(src));
}
__device__ __forceinline__ void cpa_commit() { asm volatile("cp.async.commit_group;"); }
template <int N>
__device__ __forceinline__ void cpa_wait() { asm volatile("cp.async.wait_group %0;" :: "n"(N)); }

// ---------------- kernel 1: fused convs + BN + ReLU (4 pixels / block) ----------------
__global__ __launch_bounds__(256) void prep_kernel(const float* __restrict__ x,
    const float* __restrict__ Wq, const float* __restrict__ bq,
    const float* __restrict__ gq, const float* __restrict__ betaq,
    const float* __restrict__ mq, const float* __restrict__ vq,
    const float* __restrict__ Wk, const float* __restrict__ bk,
    const float* __restrict__ gk, const float* __restrict__ betak,
    const float* __restrict__ mk, const float* __restrict__ vk,
    const float* __restrict__ Wv, const float* __restrict__ bv)
{
    __shared__ float xc[6][C_];
    __shared__ float xu[4][C_];
    __shared__ float xd[4][C_];
    int pix0 = blockIdx.x * 4;
    int b = pix0 / HW_;
    int n0 = pix0 - b * HW_;
    int h = n0 / W_, w0 = n0 - h * W_;
    int t = threadIdx.x;
    const float* xb = x + (size_t)b * HW_ * C_;

    for (int i = t; i < 6 * C_; i += 256) {
        int j = i >> 6, c = i & 63, wi = w0 - 1 + j;
        xc[j][c] = (wi >= 0 && wi < W_) ? xb[(h * W_ + wi) * C_ + c] : 0.f;
    }
    for (int i = t; i < 4 * C_; i += 256) {
        int j = i >> 6, c = i & 63;
        xu[j][c] = (h > 0)      ? xb[((h - 1) * W_ + w0 + j) * C_ + c] : 0.f;
        xd[j][c] = (h < H_ - 1) ? xb[((h + 1) * W_ + w0 + j) * C_ + c] : 0.f;
    }
    __syncthreads();

    int px = t >> 6, c = t & 63;
    int pix = pix0 + px;

    float acc = bv[c];
    #pragma unroll 8
    for (int ci = 0; ci < C_; ci++)
        acc = fmaf(xc[px + 1][ci], Wv[ci * C_ + c], acc);
    g_v[(size_t)pix * C_ + c] = acc;

    if (c < CQ) {
        float s = 0.f;
        #pragma unroll 8
        for (int ci = 0; ci < C_; ci++) {
            s = fmaf(xc[px    ][ci], Wq[(0 * C_ + ci) * CQ + c], s);
            s = fmaf(xc[px + 1][ci], Wq[(1 * C_ + ci) * CQ + c], s);
            s = fmaf(xc[px + 2][ci], Wq[(2 * C_ + ci) * CQ + c], s);
        }
        float sc  = gq[c] * rsqrtf(vq[c] + EPS_);
        float val = fmaf(s + bq[c] - mq[c], sc, betaq[c]);
        g_q[pix * CQ + c] = fmaxf(val, 0.f);
    } else if (c < 2 * CQ) {
        int cc = c - CQ;
        float s = 0.f;
        #pragma unroll 8
        for (int ci = 0; ci < C_; ci++) {
            s = fmaf(xu[px    ][ci], Wk[(0 * C_ + ci) * CQ + cc], s);
            s = fmaf(xc[px + 1][ci], Wk[(1 * C_ + ci) * CQ + cc], s);
            s = fmaf(xd[px    ][ci], Wk[(2 * C_ + ci) * CQ + cc], s);
        }
        float sc  = gk[cc] * rsqrtf(vk[cc] + EPS_);
        float val = fmaf(s + bk[cc] - mk[cc], sc, betak[cc]);
        g_k[pix * CQ + cc] = fmaxf(val, 0.f);
    }
}

// ---------------- kernel 2: softmax-denominator partials ----------------
// grid (72, B, MZ_): block owns 128 n-rows, sweeps 1/MZ_ of m via smem-staged K chunks
__global__ __launch_bounds__(256) void stats_kernel()
{
    __shared__ float ks[2][128][12];   // K chunk, padded (conflict-free frag reads)
    int b  = blockIdx.y;
    int n0 = blockIdx.x * 128;
    int mz = blockIdx.z;
    int m_base = mz * (HW_ / MZ_);
    int t = threadIdx.x, lane = t & 31, w = t >> 5;
    int g = lane >> 2, tq = lane & 3;
    size_t bHW = (size_t)b * HW_;
    const float* kb = &g_k[bHW * 8];

    unsigned bq[4];
    {
        const float* qp = &g_q[(bHW + n0 + 16 * w + g) * 8];
        bq[0] = f2tf32(qp[tq]);
        bq[1] = f2tf32(qp[tq + 4]);
        bq[2] = f2tf32(qp[64 + tq]);
        bq[3] = f2tf32(qp[64 + tq + 4]);
    }

    // prefetch chunk 0: 128 rows x 8 floats, 256 x 16B
    {
        int row = t >> 1, seg = t & 1;
        cpa16(&ks[0][row][seg * 4], kb + (m_base + row) * 8 + seg * 4);
        cpa_commit();
    }

    float cs0 = 0.f, cs1 = 0.f, cs2 = 0.f, cs3 = 0.f;

    for (int ch = 0; ch < MCH; ch++) {
        int buf = ch & 1;
        if (ch + 1 < MCH) {
            int row = t >> 1, seg = t & 1;
            cpa16(&ks[buf ^ 1][row][seg * 4], kb + (m_base + (ch + 1) * 128 + row) * 8 + seg * 4);
            cpa_commit();
            cpa_wait<1>();
        } else {
            cpa_wait<0>();
        }
        __syncthreads();

        #pragma unroll
        for (int i = 0; i < 8; i++) {
            unsigned a[4];
            a[0] = f2tf32(ks[buf][16 * i + g    ][tq    ]);
            a[1] = f2tf32(ks[buf][16 * i + g + 8][tq    ]);
            a[2] = f2tf32(ks[buf][16 * i + g    ][tq + 4]);
            a[3] = f2tf32(ks[buf][16 * i + g + 8][tq + 4]);
            float d[4] = {0.f, 0.f, 0.f, 0.f};
            float e[4] = {0.f, 0.f, 0.f, 0.f};
            mma_tf32(d, a, bq[0], bq[1]);
            mma_tf32(e, a, bq[2], bq[3]);
            cs0 += __expf(d[0]) + __expf(d[2]);
            cs1 += __expf(d[1]) + __expf(d[3]);
            cs2 += __expf(e[0]) + __expf(e[2]);
            cs3 += __expf(e[1]) + __expf(e[3]);
        }
        __syncthreads();
    }

    #pragma unroll
    for (int s = 16; s >= 4; s >>= 1) {
        cs0 += __shfl_xor_sync(0xffffffffu, cs0, s);
        cs1 += __shfl_xor_sync(0xffffffffu, cs1, s);
        cs2 += __shfl_xor_sync(0xffffffffu, cs2, s);
        cs3 += __shfl_xor_sync(0xffffffffu, cs3, s);
    }
    if (lane < 4) {
        float* rp = &g_part[((b * MZ_) + mz) * HW_ + n0 + 16 * w];
        rp[2 * tq]     = cs0;
        rp[2 * tq + 1] = cs1;
        rp[2 * tq + 8] = cs2;
        rp[2 * tq + 9] = cs3;
    }
}

// ---------------- kernel 2b: reduce partials -> rowsum ----------------
__global__ void rsum_kernel()
{
    int i = blockIdx.x * 256 + threadIdx.x;   // over BHW
    int b = i / HW_, n = i - b * HW_;
    float s = 0.f;
    #pragma unroll
    for (int mz = 0; mz < MZ_; mz++)
        s += g_part[((b * MZ_) + mz) * HW_ + n];
    g_rsum[i] = s;
}

// ---------------- kernel 3: Vs^T = bf16(gamma * v / rowsum), [b][c][n] ----------------
__global__ void scalev_kernel(const float* __restrict__ gamma)
{
    size_t o = (size_t)blockIdx.x * 256 + threadIdx.x;  // over B*C*HW, n fastest
    int n = (int)(o % HW_);
    int c = (int)((o / HW_) % C_);
    int b = (int)(o / ((size_t)HW_ * C_));
    float val = g_v[((size_t)(b * HW_ + n)) * C_ + c] * gamma[0] / g_rsum[b * HW_ + n];
    g_vsT[o] = __float2bfloat16(val);
}

// ---------------- kernel 4: fused P-recompute + bf16 GEMM + residual ----------------
// block = 64 m x 64 c output, 256 threads, 2 CTAs/SM; n chunks of 128, dbuf smem
#define PS_OFF   0
#define VS_OFF   34816
#define SMEM_TOT (VS_OFF + 34816)   // 69632 bytes

__global__ __launch_bounds__(256, 2)
void fused_kernel(const float* __restrict__ x, float* __restrict__ out)
{
    extern __shared__ __align__(16) char smem_raw[];
    __nv_bfloat16* PsB = (__nv_bfloat16*)(smem_raw + PS_OFF);   // [2][64][136] (m rows)
    __nv_bfloat16* VsB = (__nv_bfloat16*)(smem_raw + VS_OFF);   // [2][64][136] (c rows)
#define PS(bf, r, c) PsB[(bf) * (64 * 136) + (r) * 136 + (c)]
#define VS(bf, r, c) VsB[(bf) * (64 * 136) + (r) * 136 + (c)]

    int b   = blockIdx.y;
    int bm0 = blockIdx.x * 64;
    int t = threadIdx.x, lane = t & 31, w = t >> 5;     // 8 warps
    int g = lane >> 2, tq = lane & 3;
    int wc = w & 3;        // c quarter (16 rows)
    int wm = w >> 2;       // m half (32 cols)
    size_t bHW = (size_t)b * HW_;
    const float* kb = &g_k[bHW * 8];
    const __nv_bfloat16* Ag = &g_vsT[(size_t)b * C_ * HW_];

    // preload K A-fragments for this block's 64 m rows (fixed all kernel)
    unsigned ka[4][4];
    #pragma unroll
    for (int i = 0; i < 4; i++) {
        ka[i][0] = f2tf32(kb[(bm0 + 16 * i + g    ) * 8 + tq    ]);
        ka[i][1] = f2tf32(kb[(bm0 + 16 * i + g + 8) * 8 + tq    ]);
        ka[i][2] = f2tf32(kb[(bm0 + 16 * i + g    ) * 8 + tq + 4]);
        ka[i][3] = f2tf32(kb[(bm0 + 16 * i + g + 8) * 8 + tq + 4]);
    }

    // prefetch Vs chunk 0 (64 c-rows x 128 n = 1024 x 16B)
    {
        #pragma unroll
        for (int j = 0; j < 4; j++) {
            int idx = t + j * 256, row = idx >> 4, seg = idx & 15;
            cpa16(&VS(0, row, seg * 8), Ag + (size_t)row * HW_ + seg * 8);
        }
        cpa_commit();
    }

    float acc[4][4];
    #pragma unroll
    for (int i = 0; i < 4; i++)
        #pragma unroll
        for (int j = 0; j < 4; j++) acc[i][j] = 0.f;

    // Q B-fragments for chunk 0 (warp owns n-slice [16w, 16w+16), two octets)
    unsigned bq[4];
    {
        const float* qp = &g_q[(bHW + 16 * w + g) * 8];
        bq[0] = f2tf32(qp[tq]);      bq[1] = f2tf32(qp[tq + 4]);
        bq[2] = f2tf32(qp[64 + tq]); bq[3] = f2tf32(qp[64 + tq + 4]);
    }
    cpa_wait<0>();
    __syncthreads();

    int c0 = 16 * w + 2 * tq;
    // produce Ps[0] for chunk 0
    #pragma unroll
    for (int i = 0; i < 4; i++) {
        float d[4] = {0.f, 0.f, 0.f, 0.f};
        float e[4] = {0.f, 0.f, 0.f, 0.f};
        mma_tf32(d, ka[i], bq[0], bq[1]);
        mma_tf32(e, ka[i], bq[2], bq[3]);
        *(unsigned*)&PS(0, 16 * i + g,     c0    ) = packbf2(__expf(d[1]), __expf(d[0]));
        *(unsigned*)&PS(0, 16 * i + g + 8, c0    ) = packbf2(__expf(d[3]), __expf(d[2]));
        *(unsigned*)&PS(0, 16 * i + g,     c0 + 8) = packbf2(__expf(e[1]), __expf(e[0]));
        *(unsigned*)&PS(0, 16 * i + g + 8, c0 + 8) = packbf2(__expf(e[3]), __expf(e[2]));
    }
    __syncthreads();

    for (int ck = 0; ck < NMT; ck++) {
        int buf = ck & 1;
        bool more = (ck + 1 < NMT);
        unsigned bqn[4] = {0, 0, 0, 0};
        if (more) {
            int n1 = (ck + 1) * 128;
            #pragma unroll
            for (int j = 0; j < 4; j++) {
                int idx = t + j * 256, row = idx >> 4, seg = idx & 15;
                cpa16(&VS(buf ^ 1, row, seg * 8), Ag + (size_t)row * HW_ + n1 + seg * 8);
            }
            cpa_commit();
            const float* qp = &g_q[(bHW + n1 + 16 * w + g) * 8];
            bqn[0] = f2tf32(qp[tq]);      bqn[1] = f2tf32(qp[tq + 4]);
            bqn[2] = f2tf32(qp[64 + tq]); bqn[3] = f2tf32(qp[64 + tq + 4]);
        }

        #pragma unroll
        for (int i = 0; i < 4; i++) {
            // produce subtile i of chunk ck+1 into PS[buf^1]
            if (more) {
                float d[4] = {0.f, 0.f, 0.f, 0.f};
                float e[4] = {0.f, 0.f, 0.f, 0.f};
                mma_tf32(d, ka[i], bqn[0], bqn[1]);
                mma_tf32(e, ka[i], bqn[2], bqn[3]);
                *(unsigned*)&PS(buf ^ 1, 16 * i + g,     c0    ) = packbf2(__expf(d[1]), __expf(d[0]));
                *(unsigned*)&PS(buf ^ 1, 16 * i + g + 8, c0    ) = packbf2(__expf(d[3]), __expf(d[2]));
                *(unsigned*)&PS(buf ^ 1, 16 * i + g,     c0 + 8) = packbf2(__expf(e[1]), __expf(e[0]));
                *(unsigned*)&PS(buf ^ 1, 16 * i + g + 8, c0 + 8) = packbf2(__expf(e[3]), __expf(e[2]));
            }
            // GEMM k-steps 2i, 2i+1 on chunk ck
            #pragma unroll
            for (int s = 0; s < 2; s++) {
                int k0 = (2 * i + s) * 16;
                unsigned af[4];
                ldsm4(af, &VS(buf, 16 * wc + (lane & 7) + ((lane >> 3) & 1) * 8,
                              (lane >> 4) * 8 + k0));
                #pragma unroll
                for (int p = 0; p < 2; p++) {
                    unsigned bb[4];
                    ldsm4(bb, &PS(buf, 32 * wm + 16 * p + (lane & 7) + ((lane >> 4) & 1) * 8,
                                  k0 + ((lane >> 3) & 1) * 8));
                    mma_bf16(acc[2 * p    ], af, bb[0], bb[1]);
                    mma_bf16(acc[2 * p + 1], af, bb[2], bb[3]);
                }
            }
        }
        cpa_wait<0>();
        __syncthreads();
    }

    // epilogue: out[b][m][c] = D[c][m] + x[b][m][c]
    int cc0 = 16 * wc + g;
    #pragma unroll
    for (int jo = 0; jo < 4; jo++) {
        int m = bm0 + 32 * wm + 8 * jo + 2 * tq;
        size_t i00 = (bHW + m) * (size_t)C_ + cc0;
        out[i00]          = acc[jo][0] + x[i00];
        out[i00 + C_]     = acc[jo][1] + x[i00 + C_];
        out[i00 + 8]      = acc[jo][2] + x[i00 + 8];
        out[i00 + C_ + 8] = acc[jo][3] + x[i00 + C_ + 8];
    }
#undef PS
#undef VS
}

// ---------------- launch ----------------
extern "C" void kernel_launch(void* const* d_in, const int* in_sizes, int n_in,
                              void* d_out, int out_size)
{
    const float* x     = (const float*)d_in[0];
    const float* Wq    = (const float*)d_in[1];
    const float* bq    = (const float*)d_in[2];
    const float* gq    = (const float*)d_in[3];
    const float* betaq = (const float*)d_in[4];
    const float* mq    = (const float*)d_in[5];
    const float* vq    = (const float*)d_in[6];
    const float* Wk    = (const float*)d_in[7];
    const float* bk    = (const float*)d_in[8];
    const float* gk    = (const float*)d_in[9];
    const float* betak = (const float*)d_in[10];
    const float* mk    = (const float*)d_in[11];
    const float* vk    = (const float*)d_in[12];
    const float* Wv    = (const float*)d_in[13];
    const float* bv    = (const float*)d_in[14];
    const float* gamma = (const float*)d_in[15];
    float* out = (float*)d_out;

    // unconditional, idempotent; host-side attribute set (not a stream op)
    cudaFuncSetAttribute(fused_kernel, cudaFuncAttributeMaxDynamicSharedMemorySize, SMEM_TOT);

    prep_kernel<<<BHW / 4, 256>>>(x, Wq, bq, gq, betaq, mq, vq,
                                  Wk, bk, gk, betak, mk, vk, Wv, bv);
    stats_kernel<<<dim3(NMT, B_, MZ_), 256>>>();
    rsum_kernel<<<BHW / 256, 256>>>();
    scalev_kernel<<<(unsigned)(((size_t)B_ * C_ * HW_) / 256), 256>>>(gamma);
    fused_kernel<<<dim3(HW_ / 64, B_), 256, SMEM_TOT>>>(x, out);
}

// round 8
// speedup vs baseline: 1.6697x; 1.0383x over previous
#include <cuda_runtime.h>
#include <cuda_bf16.h>
#include <cstdint>

#define EPS_ 1e-3f
#define LOG2E 1.4426950408889634f
#define B_   2
#define H_   96
#define W_   96
#define C_   64
#define CQ   8
#define HW_  9216
#define BHW  (B_*HW_)
#define NMT  72            // number of 128-wide n-chunks
#define MZ_  8             // m-splits in stats
#define MCH  (NMT / MZ_)   // chunks of 128 m per stats block

// ---------------- scratch (static device arrays; no allocation) ----------------
__device__ unsigned       g_q[BHW * CQ];                // Q' = tf32(q * log2e) bits [n][8]
__device__ unsigned       g_k[BHW * CQ];                // K  = tf32(k) bits [m][8]
__device__ float          g_v[BHW * C_];                // V rows, fp32 [n][c]
__device__ __nv_bfloat16  g_vsT[(size_t)B_ * C_ * HW_]; // Vs^T [b][c][n], bf16
__device__ float          g_part[B_ * MZ_ * HW_];       // stats partials [b][mz][n]
__device__ float          g_rsum[BHW];                  // softmax denominators

// ---------------- helpers ----------------
__device__ __forceinline__ unsigned f2tf32(float f) {
    unsigned r;
    asm("cvt.rna.tf32.f32 %0, %1;" : "=r"(r) : "f"(f));
    return r;
}
__device__ __forceinline__ float ex2(float x) {
    float r;
    asm("ex2.approx.f32 %0, %1;" : "=f"(r) : "f"(x));
    return r;
}
__device__ __forceinline__ unsigned packbf2(float hi, float lo) {
    unsigned r;
    asm("cvt.rn.bf16x2.f32 %0, %1, %2;" : "=r"(r) : "f"(hi), "f"(lo));
    return r;
}
__device__ __forceinline__ void mma_tf32(float* d, const unsigned* a, unsigned b0, unsigned b1) {
    asm volatile(
        "mma.sync.aligned.m16n8k8.row.col.f32.tf32.tf32.f32 "
        "{%0,%1,%2,%3}, {%4,%5,%6,%7}, {%8,%9}, {%0,%1,%2,%3};\n"
        : "+f"(d[0]), "+f"(d[1]), "+f"(d[2]), "+f"(d[3])
        : "r"(a[0]), "r"(a[1]), "r"(a[2]), "r"(a[3]), "r"(b0), "r"(b1));
}
__device__ __forceinline__ void mma_bf16(float* d, const unsigned* a, unsigned b0, unsigned b1) {
    asm volatile(
        "mma.sync.aligned.m16n8k16.row.col.f32.bf16.bf16.f32 "
        "{%0,%1,%2,%3}, {%4,%5,%6,%7}, {%8,%9}, {%0,%1,%2,%3};\n"
        : "+f"(d[0]), "+f"(d[1]), "+f"(d[2]), "+f"(d[3])
        : "r"(a[0]), "r"(a[1]), "r"(a[2]), "r"(a[3]), "r"(b0), "r"(b1));
}
__device__ __forceinline__ void ldsm4(unsigned* r, const void* p) {
    unsigned a = (unsigned)__cvta_generic_to_shared(p);
    asm volatile("ldmatrix.sync.aligned.m8n8.x4.shared.b16 {%0,%1,%2,%3}, [%4];"
                 : "=r"(r[0]), "=r"(r[1]), "=r"(r[2]), "=r"(r[3]) : "r"(a));
}
__device__ __forceinline__ void cpa16(void* dst, const void* src) {
    unsigned d = (unsigned)__cvta_generic_to_shared(dst);
    asm volatile("cp.async.cg.shared.global [%0], [%1], 16;" :: "r"(d), "l"(src));
}
__device__ __forceinline__ void cpa_commit() { asm volatile("cp.async.commit_group;"); }
template <int N>
__device__ __forceinline__ void cpa_wait() { asm volatile("cp.async.wait_group %0;" :: "n"(N)); }

// ---------------- kernel 1: fused convs + BN + ReLU (4 pixels / block) ----------------
__global__ __launch_bounds__(256) void prep_kernel(const float* __restrict__ x,
    const float* __restrict__ Wq, const float* __restrict__ bq,
    const float* __restrict__ gq, const float* __restrict__ betaq,
    const float* __restrict__ mq, const float* __restrict__ vq,
    const float* __restrict__ Wk, const float* __restrict__ bk,
    const float* __restrict__ gk, const float* __restrict__ betak,
    const float* __restrict__ mk, const float* __restrict__ vk,
    const float* __restrict__ Wv, const float* __restrict__ bv)
{
    __shared__ float xc[6][C_];
    __shared__ float xu[4][C_];
    __shared__ float xd[4][C_];
    int pix0 = blockIdx.x * 4;
    int b = pix0 / HW_;
    int n0 = pix0 - b * HW_;
    int h = n0 / W_, w0 = n0 - h * W_;
    int t = threadIdx.x;
    const float* xb = x + (size_t)b * HW_ * C_;

    for (int i = t; i < 6 * C_; i += 256) {
        int j = i >> 6, c = i & 63, wi = w0 - 1 + j;
        xc[j][c] = (wi >= 0 && wi < W_) ? xb[(h * W_ + wi) * C_ + c] : 0.f;
    }
    for (int i = t; i < 4 * C_; i += 256) {
        int j = i >> 6, c = i & 63;
        xu[j][c] = (h > 0)      ? xb[((h - 1) * W_ + w0 + j) * C_ + c] : 0.f;
        xd[j][c] = (h < H_ - 1) ? xb[((h + 1) * W_ + w0 + j) * C_ + c] : 0.f;
    }
    __syncthreads();

    int px = t >> 6, c = t & 63;
    int pix = pix0 + px;

    float acc = bv[c];
    #pragma unroll 8
    for (int ci = 0; ci < C_; ci++)
        acc = fmaf(xc[px + 1][ci], Wv[ci * C_ + c], acc);
    g_v[(size_t)pix * C_ + c] = acc;

    if (c < CQ) {
        float s = 0.f;
        #pragma unroll 8
        for (int ci = 0; ci < C_; ci++) {
            s = fmaf(xc[px    ][ci], Wq[(0 * C_ + ci) * CQ + c], s);
            s = fmaf(xc[px + 1][ci], Wq[(1 * C_ + ci) * CQ + c], s);
            s = fmaf(xc[px + 2][ci], Wq[(2 * C_ + ci) * CQ + c], s);
        }
        float sc  = gq[c] * rsqrtf(vq[c] + EPS_);
        float val = fmaf(s + bq[c] - mq[c], sc, betaq[c]);
        g_q[pix * CQ + c] = f2tf32(fmaxf(val, 0.f) * LOG2E);   // fold log2e, pre-round
    } else if (c < 2 * CQ) {
        int cc = c - CQ;
        float s = 0.f;
        #pragma unroll 8
        for (int ci = 0; ci < C_; ci++) {
            s = fmaf(xu[px    ][ci], Wk[(0 * C_ + ci) * CQ + cc], s);
            s = fmaf(xc[px + 1][ci], Wk[(1 * C_ + ci) * CQ + cc], s);
            s = fmaf(xd[px    ][ci], Wk[(2 * C_ + ci) * CQ + cc], s);
        }
        float sc  = gk[cc] * rsqrtf(vk[cc] + EPS_);
        float val = fmaf(s + bk[cc] - mk[cc], sc, betak[cc]);
        g_k[pix * CQ + cc] = f2tf32(fmaxf(val, 0.f));          // pre-round to tf32
    }
}

// ---------------- kernel 2: softmax-denominator partials ----------------
// grid (72, B, MZ_): block owns 128 n-rows, sweeps 1/MZ_ of m via smem-staged K chunks
__global__ __launch_bounds__(256) void stats_kernel()
{
    __shared__ unsigned ks[2][128][12];   // K chunk (tf32 bits), padded
    int b  = blockIdx.y;
    int n0 = blockIdx.x * 128;
    int mz = blockIdx.z;
    int m_base = mz * (HW_ / MZ_);
    int t = threadIdx.x, lane = t & 31, w = t >> 5;
    int g = lane >> 2, tq = lane & 3;
    size_t bHW = (size_t)b * HW_;
    const unsigned* kb = &g_k[bHW * 8];

    unsigned bq[4];
    {
        const unsigned* qp = &g_q[(bHW + n0 + 16 * w + g) * 8];
        bq[0] = qp[tq];
        bq[1] = qp[tq + 4];
        bq[2] = qp[64 + tq];
        bq[3] = qp[64 + tq + 4];
    }

    // prefetch chunk 0: 128 rows x 8 words, 256 x 16B
    {
        int row = t >> 1, seg = t & 1;
        cpa16(&ks[0][row][seg * 4], kb + (m_base + row) * 8 + seg * 4);
        cpa_commit();
    }

    float cs0 = 0.f, cs1 = 0.f, cs2 = 0.f, cs3 = 0.f;

    for (int ch = 0; ch < MCH; ch++) {
        int buf = ch & 1;
        if (ch + 1 < MCH) {
            int row = t >> 1, seg = t & 1;
            cpa16(&ks[buf ^ 1][row][seg * 4], kb + (m_base + (ch + 1) * 128 + row) * 8 + seg * 4);
            cpa_commit();
            cpa_wait<1>();
        } else {
            cpa_wait<0>();
        }
        __syncthreads();

        #pragma unroll
        for (int i = 0; i < 8; i++) {
            unsigned a[4];
            a[0] = ks[buf][16 * i + g    ][tq    ];
            a[1] = ks[buf][16 * i + g + 8][tq    ];
            a[2] = ks[buf][16 * i + g    ][tq + 4];
            a[3] = ks[buf][16 * i + g + 8][tq + 4];
            float d[4] = {0.f, 0.f, 0.f, 0.f};
            float e[4] = {0.f, 0.f, 0.f, 0.f};
            mma_tf32(d, a, bq[0], bq[1]);
            mma_tf32(e, a, bq[2], bq[3]);
            cs0 += ex2(d[0]) + ex2(d[2]);
            cs1 += ex2(d[1]) + ex2(d[3]);
            cs2 += ex2(e[0]) + ex2(e[2]);
            cs3 += ex2(e[1]) + ex2(e[3]);
        }
        __syncthreads();
    }

    #pragma unroll
    for (int s = 16; s >= 4; s >>= 1) {
        cs0 += __shfl_xor_sync(0xffffffffu, cs0, s);
        cs1 += __shfl_xor_sync(0xffffffffu, cs1, s);
        cs2 += __shfl_xor_sync(0xffffffffu, cs2, s);
        cs3 += __shfl_xor_sync(0xffffffffu, cs3, s);
    }
    if (lane < 4) {
        float* rp = &g_part[((b * MZ_) + mz) * HW_ + n0 + 16 * w];
        rp[2 * tq]     = cs0;
        rp[2 * tq + 1] = cs1;
        rp[2 * tq + 8] = cs2;
        rp[2 * tq + 9] = cs3;
    }
}

// ---------------- kernel 2b: reduce partials -> rowsum ----------------
__global__ void rsum_kernel()
{
    int i = blockIdx.x * 256 + threadIdx.x;   // over BHW
    int b = i / HW_, n = i - b * HW_;
    float s = 0.f;
    #pragma unroll
    for (int mz = 0; mz < MZ_; mz++)
        s += g_part[((b * MZ_) + mz) * HW_ + n];
    g_rsum[i] = s;
}

// ---------------- kernel 3: Vs^T = bf16(gamma * v / rowsum), [b][c][n] ----------------
__global__ void scalev_kernel(const float* __restrict__ gamma)
{
    size_t o = (size_t)blockIdx.x * 256 + threadIdx.x;  // over B*C*HW, n fastest
    int n = (int)(o % HW_);
    int c = (int)((o / HW_) % C_);
    int b = (int)(o / ((size_t)HW_ * C_));
    float val = g_v[((size_t)(b * HW_ + n)) * C_ + c] * gamma[0] / g_rsum[b * HW_ + n];
    g_vsT[o] = __float2bfloat16(val);
}

// ---------------- kernel 4: fused P-recompute + bf16 GEMM + residual ----------------
// block = 64 m x 64 c output, 256 threads, 2 CTAs/SM; n chunks of 128, dbuf smem
#define PS_OFF   0
#define VS_OFF   34816
#define SMEM_TOT (VS_OFF + 34816)   // 69632 bytes

__global__ __launch_bounds__(256, 2)
void fused_kernel(const float* __restrict__ x, float* __restrict__ out)
{
    extern __shared__ __align__(16) char smem_raw[];
    __nv_bfloat16* PsB = (__nv_bfloat16*)(smem_raw + PS_OFF);   // [2][64][136] (m rows)
    __nv_bfloat16* VsB = (__nv_bfloat16*)(smem_raw + VS_OFF);   // [2][64][136] (c rows)
#define PS(bf, r, c) PsB[(bf) * (64 * 136) + (r) * 136 + (c)]
#define VS(bf, r, c) VsB[(bf) * (64 * 136) + (r) * 136 + (c)]

    int b   = blockIdx.y;
    int bm0 = blockIdx.x * 64;
    int t = threadIdx.x, lane = t & 31, w = t >> 5;     // 8 warps
    int g = lane >> 2, tq = lane & 3;
    int wc = w & 3;        // c quarter (16 rows)
    int wm = w >> 2;       // m half (32 cols)
    size_t bHW = (size_t)b * HW_;
    const unsigned* kb = &g_k[bHW * 8];
    const __nv_bfloat16* Ag = &g_vsT[(size_t)b * C_ * HW_];

    // K A-fragments for this block's 64 m rows (tf32 bits, fixed all kernel)
    unsigned ka[4][4];
    #pragma unroll
    for (int i = 0; i < 4; i++) {
        ka[i][0] = kb[(bm0 + 16 * i + g    ) * 8 + tq    ];
        ka[i][1] = kb[(bm0 + 16 * i + g + 8) * 8 + tq    ];
        ka[i][2] = kb[(bm0 + 16 * i + g    ) * 8 + tq + 4];
        ka[i][3] = kb[(bm0 + 16 * i + g + 8) * 8 + tq + 4];
    }

    // prefetch Vs chunk 0 (64 c-rows x 128 n = 1024 x 16B)
    {
        #pragma unroll
        for (int j = 0; j < 4; j++) {
            int idx = t + j * 256, row = idx >> 4, seg = idx & 15;
            cpa16(&VS(0, row, seg * 8), Ag + (size_t)row * HW_ + seg * 8);
        }
        cpa_commit();
    }

    float acc[4][4];
    #pragma unroll
    for (int i = 0; i < 4; i++)
        #pragma unroll
        for (int j = 0; j < 4; j++) acc[i][j] = 0.f;

    // Q B-fragments for chunk 0 (warp owns n-slice [16w, 16w+16), two octets)
    unsigned bq[4];
    {
        const unsigned* qp = &g_q[(bHW + 16 * w + g) * 8];
        bq[0] = qp[tq];      bq[1] = qp[tq + 4];
        bq[2] = qp[64 + tq]; bq[3] = qp[64 + tq + 4];
    }
    cpa_wait<0>();
    __syncthreads();

    int c0 = 16 * w + 2 * tq;
    // produce Ps[0] for chunk 0
    #pragma unroll
    for (int i = 0; i < 4; i++) {
        float d[4] = {0.f, 0.f, 0.f, 0.f};
        float e[4] = {0.f, 0.f, 0.f, 0.f};
        mma_tf32(d, ka[i], bq[0], bq[1]);
        mma_tf32(e, ka[i], bq[2], bq[3]);
        *(unsigned*)&PS(0, 16 * i + g,     c0    ) = packbf2(ex2(d[1]), ex2(d[0]));
        *(unsigned*)&PS(0, 16 * i + g + 8, c0    ) = packbf2(ex2(d[3]), ex2(d[2]));
        *(unsigned*)&PS(0, 16 * i + g,     c0 + 8) = packbf2(ex2(e[1]), ex2(e[0]));
        *(unsigned*)&PS(0, 16 * i + g + 8, c0 + 8) = packbf2(ex2(e[3]), ex2(e[2]));
    }
    __syncthreads();

    for (int ck = 0; ck < NMT; ck++) {
        int buf = ck & 1;
        bool more = (ck + 1 < NMT);
        unsigned bqn[4] = {0, 0, 0, 0};
        if (more) {
            int n1 = (ck + 1) * 128;
            #pragma unroll
            for (int j = 0; j < 4; j++) {
                int idx = t + j * 256, row = idx >> 4, seg = idx & 15;
                cpa16(&VS(buf ^ 1, row, seg * 8), Ag + (size_t)row * HW_ + n1 + seg * 8);
            }
            cpa_commit();
            const unsigned* qp = &g_q[(bHW + n1 + 16 * w + g) * 8];
            bqn[0] = qp[tq];      bqn[1] = qp[tq + 4];
            bqn[2] = qp[64 + tq]; bqn[3] = qp[64 + tq + 4];
        }

        #pragma unroll
        for (int i = 0; i < 4; i++) {
            // produce subtile i of chunk ck+1 into PS[buf^1]
            if (more) {
                float d[4] = {0.f, 0.f, 0.f, 0.f};
                float e[4] = {0.f, 0.f, 0.f, 0.f};
                mma_tf32(d, ka[i], bqn[0], bqn[1]);
                mma_tf32(e, ka[i], bqn[2], bqn[3]);
                *(unsigned*)&PS(buf ^ 1, 16 * i + g,     c0    ) = packbf2(ex2(d[1]), ex2(d[0]));
                *(unsigned*)&PS(buf ^ 1, 16 * i + g + 8, c0    ) = packbf2(ex2(d[3]), ex2(d[2]));
                *(unsigned*)&PS(buf ^ 1, 16 * i + g,     c0 + 8) = packbf2(ex2(e[1]), ex2(e[0]));
                *(unsigned*)&PS(buf ^ 1, 16 * i + g + 8, c0 + 8) = packbf2(ex2(e[3]), ex2(e[2]));
            }
            // GEMM k-steps 2i, 2i+1 on chunk ck
            #pragma unroll
            for (int s = 0; s < 2; s++) {
                int k0 = (2 * i + s) * 16;
                unsigned af[4];
                ldsm4(af, &VS(buf, 16 * wc + (lane & 7) + ((lane >> 3) & 1) * 8,
                              (lane >> 4) * 8 + k0));
                #pragma unroll
                for (int p = 0; p < 2; p++) {
                    unsigned bb[4];
                    ldsm4(bb, &PS(buf, 32 * wm + 16 * p + (lane & 7) + ((lane >> 4) & 1) * 8,
                                  k0 + ((lane >> 3) & 1) * 8));
                    mma_bf16(acc[2 * p    ], af, bb[0], bb[1]);
                    mma_bf16(acc[2 * p + 1], af, bb[2], bb[3]);
                }
            }
        }
        cpa_wait<0>();
        __syncthreads();
    }

    // epilogue: out[b][m][c] = D[c][m] + x[b][m][c]
    int cc0 = 16 * wc + g;
    #pragma unroll
    for (int jo = 0; jo < 4; jo++) {
        int m = bm0 + 32 * wm + 8 * jo + 2 * tq;
        size_t i00 = (bHW + m) * (size_t)C_ + cc0;
        out[i00]          = acc[jo][0] + x[i00];
        out[i00 + C_]     = acc[jo][1] + x[i00 + C_];
        out[i00 + 8]      = acc[jo][2] + x[i00 + 8];
        out[i00 + C_ + 8] = acc[jo][3] + x[i00 + C_ + 8];
    }
#undef PS
#undef VS
}

// ---------------- launch ----------------
extern "C" void kernel_launch(void* const* d_in, const int* in_sizes, int n_in,
                              void* d_out, int out_size)
{
    const float* x     = (const float*)d_in[0];
    const float* Wq    = (const float*)d_in[1];
    const float* bq    = (const float*)d_in[2];
    const float* gq    = (const float*)d_in[3];
    const float* betaq = (const float*)d_in[4];
    const float* mq    = (const float*)d_in[5];
    const float* vq    = (const float*)d_in[6];
    const float* Wk    = (const float*)d_in[7];
    const float* bk    = (const float*)d_in[8];
    const float* gk    = (const float*)d_in[9];
    const float* betak = (const float*)d_in[10];
    const float* mk    = (const float*)d_in[11];
    const float* vk    = (const float*)d_in[12];
    const float* Wv    = (const float*)d_in[13];
    const float* bv    = (const float*)d_in[14];
    const float* gamma = (const float*)d_in[15];
    float* out = (float*)d_out;

    // unconditional, idempotent; host-side attribute set (not a stream op)
    cudaFuncSetAttribute(fused_kernel, cudaFuncAttributeMaxDynamicSharedMemorySize, SMEM_TOT);

    prep_kernel<<<BHW / 4, 256>>>(x, Wq, bq, gq, betaq, mq, vq,
                                  Wk, bk, gk, betak, mk, vk, Wv, bv);
    stats_kernel<<<dim3(NMT, B_, MZ_), 256>>>();
    rsum_kernel<<<BHW / 256, 256>>>();
    scalev_kernel<<<(unsigned)(((size_t)B_ * C_ * HW_) / 256), 256>>>(gamma);
    fused_kernel<<<dim3(HW_ / 64, B_), 256, SMEM_TOT>>>(x, out);
}

// round 10
// speedup vs baseline: 1.8466x; 1.1059x over previous
#include <cuda_runtime.h>
#include <cuda_bf16.h>
#include <cstdint>

#define EPS_ 1e-3f
#define LOG2E 1.4426950408889634f
#define B_   2
#define H_   96
#define W_   96
#define C_   64
#define CQ   8
#define HW_  9216
#define BHW  (B_*HW_)
#define NMT  72            // number of 128-wide n-chunks
#define MZ_  8             // m-splits in stats
#define MCH  (NMT / MZ_)   // chunks of 128 m per stats block

// ---------------- scratch (static device arrays; no allocation) ----------------
__device__ unsigned       g_q[BHW * CQ];                // Q' = tf32(q * log2e) bits [n][8]
__device__ unsigned       g_k[BHW * CQ];                // K  = tf32(k) bits [m][8]
__device__ float          g_v[BHW * C_];                // V rows, fp32 [n][c]
__device__ __nv_bfloat16  g_vsT[(size_t)B_ * C_ * HW_]; // Vs^T [b][c][n], bf16
__device__ float          g_part[B_ * MZ_ * HW_];       // stats partials [b][mz][n]

// ---------------- helpers ----------------
__device__ __forceinline__ unsigned f2tf32(float f) {
    unsigned r;
    asm("cvt.rna.tf32.f32 %0, %1;" : "=r"(r) : "f"(f));
    return r;
}
__device__ __forceinline__ float ex2(float x) {
    float r;
    asm("ex2.approx.f32 %0, %1;" : "=f"(r) : "f"(x));
    return r;
}
__device__ __forceinline__ unsigned packbf2(float hi, float lo) {
    unsigned r;
    asm("cvt.rn.bf16x2.f32 %0, %1, %2;" : "=r"(r) : "f"(hi), "f"(lo));
    return r;
}
__device__ __forceinline__ void mma_tf32(float* d, const unsigned* a, unsigned b0, unsigned b1) {
    asm volatile(
        "mma.sync.aligned.m16n8k8.row.col.f32.tf32.tf32.f32 "
        "{%0,%1,%2,%3}, {%4,%5,%6,%7}, {%8,%9}, {%0,%1,%2,%3};\n"
        : "+f"(d[0]), "+f"(d[1]), "+f"(d[2]), "+f"(d[3])
        : "r"(a[0]), "r"(a[1]), "r"(a[2]), "r"(a[3]), "r"(b0), "r"(b1));
}
__device__ __forceinline__ void mma_bf16(float* d, const unsigned* a, unsigned b0, unsigned b1) {
    asm volatile(
        "mma.sync.aligned.m16n8k16.row.col.f32.bf16.bf16.f32 "
        "{%0,%1,%2,%3}, {%4,%5,%6,%7}, {%8,%9}, {%0,%1,%2,%3};\n"
        : "+f"(d[0]), "+f"(d[1]), "+f"(d[2]), "+f"(d[3])
        : "r"(a[0]), "r"(a[1]), "r"(a[2]), "r"(a[3]), "r"(b0), "r"(b1));
}
__device__ __forceinline__ void ldsm4(unsigned* r, const void* p) {
    unsigned a = (unsigned)__cvta_generic_to_shared(p);
    asm volatile("ldmatrix.sync.aligned.m8n8.x4.shared.b16 {%0,%1,%2,%3}, [%4];"
                 : "=r"(r[0]), "=r"(r[1]), "=r"(r[2]), "=r"(r[3]) : "r"(a));
}
__device__ __forceinline__ void cpa16(void* dst, const void* src) {
    unsigned d = (unsigned)__cvta_generic_to_shared(dst);
    asm volatile("cp.async.cg.shared.global [%0], [%1], 16;" :: "r"(d), "l"(src));
}
__device__ __forceinline__ void cpa_commit() { asm volatile("cp.async.commit_group;"); }
template <int N>
__device__ __forceinline__ void cpa_wait() { asm volatile("cp.async.wait_group %0;" :: "n"(N)); }

// ---------------- kernel 1: fused convs + BN + ReLU (4 pixels / block) ----------------
__global__ __launch_bounds__(256) void prep_kernel(const float* __restrict__ x,
    const float* __restrict__ Wq, const float* __restrict__ bq,
    const float* __restrict__ gq, const float* __restrict__ betaq,
    const float* __restrict__ mq, const float* __restrict__ vq,
    const float* __restrict__ Wk, const float* __restrict__ bk,
    const float* __restrict__ gk, const float* __restrict__ betak,
    const float* __restrict__ mk, const float* __restrict__ vk,
    const float* __restrict__ Wv, const float* __restrict__ bv)
{
    __shared__ float xc[6][C_];
    __shared__ float xu[4][C_];
    __shared__ float xd[4][C_];
    int pix0 = blockIdx.x * 4;
    int b = pix0 / HW_;
    int n0 = pix0 - b * HW_;
    int h = n0 / W_, w0 = n0 - h * W_;
    int t = threadIdx.x;
    const float* xb = x + (size_t)b * HW_ * C_;

    for (int i = t; i < 6 * C_; i += 256) {
        int j = i >> 6, c = i & 63, wi = w0 - 1 + j;
        xc[j][c] = (wi >= 0 && wi < W_) ? xb[(h * W_ + wi) * C_ + c] : 0.f;
    }
    for (int i = t; i < 4 * C_; i += 256) {
        int j = i >> 6, c = i & 63;
        xu[j][c] = (h > 0)      ? xb[((h - 1) * W_ + w0 + j) * C_ + c] : 0.f;
        xd[j][c] = (h < H_ - 1) ? xb[((h + 1) * W_ + w0 + j) * C_ + c] : 0.f;
    }
    __syncthreads();

    int px = t >> 6, c = t & 63;
    int pix = pix0 + px;

    float acc = bv[c];
    #pragma unroll 8
    for (int ci = 0; ci < C_; ci++)
        acc = fmaf(xc[px + 1][ci], Wv[ci * C_ + c], acc);
    g_v[(size_t)pix * C_ + c] = acc;

    if (c < CQ) {
        float s = 0.f;
        #pragma unroll 8
        for (int ci = 0; ci < C_; ci++) {
            s = fmaf(xc[px    ][ci], Wq[(0 * C_ + ci) * CQ + c], s);
            s = fmaf(xc[px + 1][ci], Wq[(1 * C_ + ci) * CQ + c], s);
            s = fmaf(xc[px + 2][ci], Wq[(2 * C_ + ci) * CQ + c], s);
        }
        float sc  = gq[c] * rsqrtf(vq[c] + EPS_);
        float val = fmaf(s + bq[c] - mq[c], sc, betaq[c]);
        g_q[pix * CQ + c] = f2tf32(fmaxf(val, 0.f) * LOG2E);
    } else if (c < 2 * CQ) {
        int cc = c - CQ;
        float s = 0.f;
        #pragma unroll 8
        for (int ci = 0; ci < C_; ci++) {
            s = fmaf(xu[px    ][ci], Wk[(0 * C_ + ci) * CQ + cc], s);
            s = fmaf(xc[px + 1][ci], Wk[(1 * C_ + ci) * CQ + cc], s);
            s = fmaf(xd[px    ][ci], Wk[(2 * C_ + ci) * CQ + cc], s);
        }
        float sc  = gk[cc] * rsqrtf(vk[cc] + EPS_);
        float val = fmaf(s + bk[cc] - mk[cc], sc, betak[cc]);
        g_k[pix * CQ + cc] = f2tf32(fmaxf(val, 0.f));
    }
}

// ---------------- kernel 2: softmax-denominator partials ----------------
__global__ __launch_bounds__(256) void stats_kernel()
{
    __shared__ unsigned ks[2][128][12];
    int b  = blockIdx.y;
    int n0 = blockIdx.x * 128;
    int mz = blockIdx.z;
    int m_base = mz * (HW_ / MZ_);
    int t = threadIdx.x, lane = t & 31, w = t >> 5;
    int g = lane >> 2, tq = lane & 3;
    size_t bHW = (size_t)b * HW_;
    const unsigned* kb = &g_k[bHW * 8];

    unsigned bq[4];
    {
        const unsigned* qp = &g_q[(bHW + n0 + 16 * w + g) * 8];
        bq[0] = qp[tq];
        bq[1] = qp[tq + 4];
        bq[2] = qp[64 + tq];
        bq[3] = qp[64 + tq + 4];
    }

    {
        int row = t >> 1, seg = t & 1;
        cpa16(&ks[0][row][seg * 4], kb + (m_base + row) * 8 + seg * 4);
        cpa_commit();
    }

    float cs0 = 0.f, cs1 = 0.f, cs2 = 0.f, cs3 = 0.f;

    for (int ch = 0; ch < MCH; ch++) {
        int buf = ch & 1;
        if (ch + 1 < MCH) {
            int row = t >> 1, seg = t & 1;
            cpa16(&ks[buf ^ 1][row][seg * 4], kb + (m_base + (ch + 1) * 128 + row) * 8 + seg * 4);
            cpa_commit();
            cpa_wait<1>();
        } else {
            cpa_wait<0>();
        }
        __syncthreads();

        #pragma unroll
        for (int i = 0; i < 8; i++) {
            unsigned a[4];
            a[0] = ks[buf][16 * i + g    ][tq    ];
            a[1] = ks[buf][16 * i + g + 8][tq    ];
            a[2] = ks[buf][16 * i + g    ][tq + 4];
            a[3] = ks[buf][16 * i + g + 8][tq + 4];
            float d[4] = {0.f, 0.f, 0.f, 0.f};
            float e[4] = {0.f, 0.f, 0.f, 0.f};
            mma_tf32(d, a, bq[0], bq[1]);
            mma_tf32(e, a, bq[2], bq[3]);
            cs0 += ex2(d[0]) + ex2(d[2]);
            cs1 += ex2(d[1]) + ex2(d[3]);
            cs2 += ex2(e[0]) + ex2(e[2]);
            cs3 += ex2(e[1]) + ex2(e[3]);
        }
        __syncthreads();
    }

    #pragma unroll
    for (int s = 16; s >= 4; s >>= 1) {
        cs0 += __shfl_xor_sync(0xffffffffu, cs0, s);
        cs1 += __shfl_xor_sync(0xffffffffu, cs1, s);
        cs2 += __shfl_xor_sync(0xffffffffu, cs2, s);
        cs3 += __shfl_xor_sync(0xffffffffu, cs3, s);
    }
    if (lane < 4) {
        float* rp = &g_part[((b * MZ_) + mz) * HW_ + n0 + 16 * w];
        rp[2 * tq]     = cs0;
        rp[2 * tq + 1] = cs1;
        rp[2 * tq + 8] = cs2;
        rp[2 * tq + 9] = cs3;
    }
}

// ---------------- kernel 3: Vs^T = bf16(gamma * v / rowsum), rowsum reduced inline ----------------
__global__ void scalev_kernel(const float* __restrict__ gamma)
{
    size_t o = (size_t)blockIdx.x * 256 + threadIdx.x;  // over B*C*HW, n fastest
    int n = (int)(o % HW_);
    int c = (int)((o / HW_) % C_);
    int b = (int)(o / ((size_t)HW_ * C_));
    float s = 0.f;
    #pragma unroll
    for (int mz = 0; mz < MZ_; mz++)
        s += g_part[((b * MZ_) + mz) * HW_ + n];
    float val = g_v[((size_t)(b * HW_ + n)) * C_ + c] * gamma[0] / s;
    g_vsT[o] = __float2bfloat16(val);
}

// ---------------- kernel 4: fused P-in-registers GEMM + residual ----------------
// block = 64 m x 64 c output, 128 threads (4 warps); warp owns 16 m-rows x all 64 c.
// Per 16-n step: P tile (16m x 16n) built in registers straight from tf32 MMA accum
// (accumulator layout == bf16 A-frag layout), consumed immediately vs Vs B-frags.
#define VSOFF   0
#define VSBUF   17408                    // 64 rows x 136 bf16
#define QSOFF   (2 * VSBUF)              // 34816
#define QSBUF   4096                     // 128 rows x 8 words
#define FK_SMEM (QSOFF + 2 * QSBUF)      // 43008

__global__ __launch_bounds__(128, 4)
void fused_kernel(const float* __restrict__ x, float* __restrict__ out)
{
    extern __shared__ __align__(16) char smem[];
    __nv_bfloat16* VsB = (__nv_bfloat16*)(smem + VSOFF);
    unsigned*      QsB = (unsigned*)(smem + QSOFF);
#define VS(bf, r, c) VsB[(bf) * (64 * 136) + (r) * 136 + (c)]

    int b  = blockIdx.y;
    int m0 = blockIdx.x * 64;
    int t = threadIdx.x, lane = t & 31, w = t >> 5;     // 4 warps
    int g = lane >> 2, tq = lane & 3;
    size_t bHW = (size_t)b * HW_;
    const unsigned* kb = &g_k[bHW * 8];
    const unsigned* qb = &g_q[bHW * 8];
    const __nv_bfloat16* Ag = &g_vsT[(size_t)b * C_ * HW_];

    // K A-fragments for this warp's 16 m-rows (fixed all kernel)
    int mw = m0 + 16 * w;
    unsigned ka[4];
    ka[0] = kb[(mw + g    ) * 8 + tq    ];
    ka[1] = kb[(mw + g + 8) * 8 + tq    ];
    ka[2] = kb[(mw + g    ) * 8 + tq + 4];
    ka[3] = kb[(mw + g + 8) * 8 + tq + 4];

    float acc[8][4];
    #pragma unroll
    for (int i = 0; i < 8; i++)
        #pragma unroll
        for (int j = 0; j < 4; j++) acc[i][j] = 0.f;

    // prefetch chunk 0: Vs (1024 x 16B) + Q (256 x 16B)
    #pragma unroll
    for (int j = 0; j < 8; j++) {
        int idx = t + j * 128, row = idx >> 4, seg = idx & 15;
        cpa16(&VS(0, row, seg * 8), Ag + (size_t)row * HW_ + seg * 8);
    }
    #pragma unroll
    for (int j = 0; j < 2; j++) {
        int idx = t + j * 128, row = idx >> 1, seg = idx & 1;
        cpa16(QsB + row * 8 + seg * 4, qb + (size_t)row * 8 + seg * 4);
    }
    cpa_commit();
    cpa_wait<0>();
    __syncthreads();

    for (int ck = 0; ck < NMT; ck++) {
        int buf = ck & 1;
        bool more = (ck + 1 < NMT);
        if (more) {
            int n1 = (ck + 1) * 128;
            #pragma unroll
            for (int j = 0; j < 8; j++) {
                int idx = t + j * 128, row = idx >> 4, seg = idx & 15;
                cpa16(&VS(buf ^ 1, row, seg * 8), Ag + (size_t)row * HW_ + n1 + seg * 8);
            }
            #pragma unroll
            for (int j = 0; j < 2; j++) {
                int idx = t + j * 128, row = idx >> 1, seg = idx & 1;
                cpa16(QsB + (buf ^ 1) * 1024 + row * 8 + seg * 4,
                      qb + (size_t)(n1 + row) * 8 + seg * 4);
            }
            cpa_commit();
        }

        const unsigned* qs = QsB + buf * 1024;
        #pragma unroll
        for (int s = 0; s < 8; s++) {
            int nb = 16 * s;
            // produce P A-frags in registers (no smem round-trip)
            unsigned q0 = qs[(nb + g    ) * 8 + tq    ];
            unsigned q1 = qs[(nb + g    ) * 8 + tq + 4];
            unsigned q2 = qs[(nb + 8 + g) * 8 + tq    ];
            unsigned q3 = qs[(nb + 8 + g) * 8 + tq + 4];
            float d[4] = {0.f, 0.f, 0.f, 0.f};
            float e[4] = {0.f, 0.f, 0.f, 0.f};
            mma_tf32(d, ka, q0, q1);                  // n-octet nb
            mma_tf32(e, ka, q2, q3);                  // n-octet nb+8
            unsigned a[4];
            a[0] = packbf2(ex2(d[1]), ex2(d[0]));     // m=g,   k=2tq,2tq+1
            a[1] = packbf2(ex2(d[3]), ex2(d[2]));     // m=g+8
            a[2] = packbf2(ex2(e[1]), ex2(e[0]));     // m=g,   k=2tq+8,+9
            a[3] = packbf2(ex2(e[3]), ex2(e[2]));     // m=g+8
            // consume vs Vs B-frags: D[m16][c64] += P(m16 x k16) x Vs(k16 x c64)
            #pragma unroll
            for (int cb = 0; cb < 4; cb++) {
                unsigned bb[4];
                ldsm4(bb, &VS(buf, cb * 16 + (lane & 7) + ((lane >> 4) & 1) * 8,
                              nb + ((lane >> 3) & 1) * 8));
                mma_bf16(acc[2 * cb    ], a, bb[0], bb[1]);
                mma_bf16(acc[2 * cb + 1], a, bb[2], bb[3]);
            }
        }
        if (more) cpa_wait<0>();
        __syncthreads();
    }

    // epilogue: out[b][m][c] = D[m][c] + x[b][m][c]
    int m = m0 + 16 * w + g;
    #pragma unroll
    for (int o = 0; o < 8; o++) {
        int c = 8 * o + 2 * tq;
        size_t i0 = (bHW + m) * (size_t)C_ + c;
        size_t i1 = i0 + 8 * C_;
        float2 x0 = *(const float2*)&x[i0];
        float2 x1 = *(const float2*)&x[i1];
        float2 o0 = { acc[o][0] + x0.x, acc[o][1] + x0.y };
        float2 o1 = { acc[o][2] + x1.x, acc[o][3] + x1.y };
        *(float2*)&out[i0] = o0;
        *(float2*)&out[i1] = o1;
    }
#undef VS
}

// ---------------- launch ----------------
extern "C" void kernel_launch(void* const* d_in, const int* in_sizes, int n_in,
                              void* d_out, int out_size)
{
    const float* x     = (const float*)d_in[0];
    const float* Wq    = (const float*)d_in[1];
    const float* bq    = (const float*)d_in[2];
    const float* gq    = (const float*)d_in[3];
    const float* betaq = (const float*)d_in[4];
    const float* mq    = (const float*)d_in[5];
    const float* vq    = (const float*)d_in[6];
    const float* Wk    = (const float*)d_in[7];
    const float* bk    = (const float*)d_in[8];
    const float* gk    = (const float*)d_in[9];
    const float* betak = (const float*)d_in[10];
    const float* mk    = (const float*)d_in[11];
    const float* vk    = (const float*)d_in[12];
    const float* Wv    = (const float*)d_in[13];
    const float* bv    = (const float*)d_in[14];
    const float* gamma = (const float*)d_in[15];
    float* out = (float*)d_out;

    // unconditional, idempotent; host-side attribute set (not a stream op)
    cudaFuncSetAttribute(fused_kernel, cudaFuncAttributeMaxDynamicSharedMemorySize, FK_SMEM);

    prep_kernel<<<BHW / 4, 256>>>(x, Wq, bq, gq, betaq, mq, vq,
                                  Wk, bk, gk, betak, mk, vk, Wv, bv);
    stats_kernel<<<dim3(NMT, B_, MZ_), 256>>>();
    scalev_kernel<<<(unsigned)(((size_t)B_ * C_ * HW_) / 256), 256>>>(gamma);
    fused_kernel<<<dim3(HW_ / 64, B_), 128, FK_SMEM>>>(x, out);
}

// round 11
// speedup vs baseline: 1.8625x; 1.0086x over previous
#include <cuda_runtime.h>
#include <cuda_bf16.h>
#include <cstdint>

#define EPS_ 1e-3f
#define LOG2E 1.4426950408889634f
#define B_   2
#define H_   96
#define W_   96
#define C_   64
#define CQ   8
#define HW_  9216
#define BHW  (B_*HW_)
#define NMT  72            // number of 128-wide n-chunks
#define MZ_  8             // m-splits in stats
#define MCH  (NMT / MZ_)   // chunks of 128 m per stats block

// ---------------- scratch (static device arrays; no allocation) ----------------
__device__ unsigned       g_q[BHW * CQ];                // Q' = tf32(q * log2e) bits [n][8]
__device__ unsigned       g_k[BHW * CQ];                // K  = tf32(k) bits [m][8]
__device__ float          g_v[BHW * C_];                // V rows, fp32 [n][c]
__device__ __nv_bfloat16  g_vsT[(size_t)B_ * C_ * HW_]; // Vs^T [b][c][n], bf16
__device__ float          g_part[B_ * MZ_ * HW_];       // stats partials [b][mz][n]

// ---------------- helpers ----------------
__device__ __forceinline__ unsigned f2tf32(float f) {
    unsigned r;
    asm("cvt.rna.tf32.f32 %0, %1;" : "=r"(r) : "f"(f));
    return r;
}
__device__ __forceinline__ float ex2(float x) {
    float r;
    asm("ex2.approx.f32 %0, %1;" : "=f"(r) : "f"(x));
    return r;
}
__device__ __forceinline__ unsigned packbf2(float hi, float lo) {
    unsigned r;
    asm("cvt.rn.bf16x2.f32 %0, %1, %2;" : "=r"(r) : "f"(hi), "f"(lo));
    return r;
}
__device__ __forceinline__ void mma_tf32(float* d, const unsigned* a, unsigned b0, unsigned b1) {
    asm volatile(
        "mma.sync.aligned.m16n8k8.row.col.f32.tf32.tf32.f32 "
        "{%0,%1,%2,%3}, {%4,%5,%6,%7}, {%8,%9}, {%0,%1,%2,%3};\n"
        : "+f"(d[0]), "+f"(d[1]), "+f"(d[2]), "+f"(d[3])
        : "r"(a[0]), "r"(a[1]), "r"(a[2]), "r"(a[3]), "r"(b0), "r"(b1));
}
__device__ __forceinline__ void mma_bf16(float* d, const unsigned* a, unsigned b0, unsigned b1) {
    asm volatile(
        "mma.sync.aligned.m16n8k16.row.col.f32.bf16.bf16.f32 "
        "{%0,%1,%2,%3}, {%4,%5,%6,%7}, {%8,%9}, {%0,%1,%2,%3};\n"
        : "+f"(d[0]), "+f"(d[1]), "+f"(d[2]), "+f"(d[3])
        : "r"(a[0]), "r"(a[1]), "r"(a[2]), "r"(a[3]), "r"(b0), "r"(b1));
}
__device__ __forceinline__ void ldsm4(unsigned* r, const void* p) {
    unsigned a = (unsigned)__cvta_generic_to_shared(p);
    asm volatile("ldmatrix.sync.aligned.m8n8.x4.shared.b16 {%0,%1,%2,%3}, [%4];"
                 : "=r"(r[0]), "=r"(r[1]), "=r"(r[2]), "=r"(r[3]) : "r"(a));
}
__device__ __forceinline__ void cpa16(void* dst, const void* src) {
    unsigned d = (unsigned)__cvta_generic_to_shared(dst);
    asm volatile("cp.async.cg.shared.global [%0], [%1], 16;" :: "r"(d), "l"(src));
}
__device__ __forceinline__ void cpa_commit() { asm volatile("cp.async.commit_group;"); }
template <int N>
__device__ __forceinline__ void cpa_wait() { asm volatile("cp.async.wait_group %0;" :: "n"(N)); }

// ---------------- kernel 1: fused convs + BN + ReLU (4 pixels / block) ----------------
__global__ __launch_bounds__(256) void prep_kernel(const float* __restrict__ x,
    const float* __restrict__ Wq, const float* __restrict__ bq,
    const float* __restrict__ gq, const float* __restrict__ betaq,
    const float* __restrict__ mq, const float* __restrict__ vq,
    const float* __restrict__ Wk, const float* __restrict__ bk,
    const float* __restrict__ gk, const float* __restrict__ betak,
    const float* __restrict__ mk, const float* __restrict__ vk,
    const float* __restrict__ Wv, const float* __restrict__ bv)
{
    __shared__ float xc[6][C_];
    __shared__ float xu[4][C_];
    __shared__ float xd[4][C_];
    int pix0 = blockIdx.x * 4;
    int b = pix0 / HW_;
    int n0 = pix0 - b * HW_;
    int h = n0 / W_, w0 = n0 - h * W_;
    int t = threadIdx.x;
    const float* xb = x + (size_t)b * HW_ * C_;

    for (int i = t; i < 6 * C_; i += 256) {
        int j = i >> 6, c = i & 63, wi = w0 - 1 + j;
        xc[j][c] = (wi >= 0 && wi < W_) ? xb[(h * W_ + wi) * C_ + c] : 0.f;
    }
    for (int i = t; i < 4 * C_; i += 256) {
        int j = i >> 6, c = i & 63;
        xu[j][c] = (h > 0)      ? xb[((h - 1) * W_ + w0 + j) * C_ + c] : 0.f;
        xd[j][c] = (h < H_ - 1) ? xb[((h + 1) * W_ + w0 + j) * C_ + c] : 0.f;
    }
    __syncthreads();

    int px = t >> 6, c = t & 63;
    int pix = pix0 + px;

    float acc = bv[c];
    #pragma unroll 8
    for (int ci = 0; ci < C_; ci++)
        acc = fmaf(xc[px + 1][ci], Wv[ci * C_ + c], acc);
    g_v[(size_t)pix * C_ + c] = acc;

    if (c < CQ) {
        float s = 0.f;
        #pragma unroll 8
        for (int ci = 0; ci < C_; ci++) {
            s = fmaf(xc[px    ][ci], Wq[(0 * C_ + ci) * CQ + c], s);
            s = fmaf(xc[px + 1][ci], Wq[(1 * C_ + ci) * CQ + c], s);
            s = fmaf(xc[px + 2][ci], Wq[(2 * C_ + ci) * CQ + c], s);
        }
        float sc  = gq[c] * rsqrtf(vq[c] + EPS_);
        float val = fmaf(s + bq[c] - mq[c], sc, betaq[c]);
        g_q[pix * CQ + c] = f2tf32(fmaxf(val, 0.f) * LOG2E);
    } else if (c < 2 * CQ) {
        int cc = c - CQ;
        float s = 0.f;
        #pragma unroll 8
        for (int ci = 0; ci < C_; ci++) {
            s = fmaf(xu[px    ][ci], Wk[(0 * C_ + ci) * CQ + cc], s);
            s = fmaf(xc[px + 1][ci], Wk[(1 * C_ + ci) * CQ + cc], s);
            s = fmaf(xd[px    ][ci], Wk[(2 * C_ + ci) * CQ + cc], s);
        }
        float sc  = gk[cc] * rsqrtf(vk[cc] + EPS_);
        float val = fmaf(s + bk[cc] - mk[cc], sc, betak[cc]);
        g_k[pix * CQ + cc] = f2tf32(fmaxf(val, 0.f));
    }
}

// ---------------- kernel 2: softmax-denominator partials ----------------
__global__ __launch_bounds__(256) void stats_kernel()
{
    __shared__ unsigned ks[2][128][12];
    int b  = blockIdx.y;
    int n0 = blockIdx.x * 128;
    int mz = blockIdx.z;
    int m_base = mz * (HW_ / MZ_);
    int t = threadIdx.x, lane = t & 31, w = t >> 5;
    int g = lane >> 2, tq = lane & 3;
    size_t bHW = (size_t)b * HW_;
    const unsigned* kb = &g_k[bHW * 8];

    unsigned bq[4];
    {
        const unsigned* qp = &g_q[(bHW + n0 + 16 * w + g) * 8];
        bq[0] = qp[tq];
        bq[1] = qp[tq + 4];
        bq[2] = qp[64 + tq];
        bq[3] = qp[64 + tq + 4];
    }

    {
        int row = t >> 1, seg = t & 1;
        cpa16(&ks[0][row][seg * 4], kb + (m_base + row) * 8 + seg * 4);
        cpa_commit();
    }

    float cs0 = 0.f, cs1 = 0.f, cs2 = 0.f, cs3 = 0.f;

    for (int ch = 0; ch < MCH; ch++) {
        int buf = ch & 1;
        if (ch + 1 < MCH) {
            int row = t >> 1, seg = t & 1;
            cpa16(&ks[buf ^ 1][row][seg * 4], kb + (m_base + (ch + 1) * 128 + row) * 8 + seg * 4);
            cpa_commit();
            cpa_wait<1>();
        } else {
            cpa_wait<0>();
        }
        __syncthreads();

        #pragma unroll
        for (int i = 0; i < 8; i++) {
            unsigned a[4];
            a[0] = ks[buf][16 * i + g    ][tq    ];
            a[1] = ks[buf][16 * i + g + 8][tq    ];
            a[2] = ks[buf][16 * i + g    ][tq + 4];
            a[3] = ks[buf][16 * i + g + 8][tq + 4];
            float d[4] = {0.f, 0.f, 0.f, 0.f};
            float e[4] = {0.f, 0.f, 0.f, 0.f};
            mma_tf32(d, a, bq[0], bq[1]);
            mma_tf32(e, a, bq[2], bq[3]);
            cs0 += ex2(d[0]) + ex2(d[2]);
            cs1 += ex2(d[1]) + ex2(d[3]);
            cs2 += ex2(e[0]) + ex2(e[2]);
            cs3 += ex2(e[1]) + ex2(e[3]);
        }
        __syncthreads();
    }

    #pragma unroll
    for (int s = 16; s >= 4; s >>= 1) {
        cs0 += __shfl_xor_sync(0xffffffffu, cs0, s);
        cs1 += __shfl_xor_sync(0xffffffffu, cs1, s);
        cs2 += __shfl_xor_sync(0xffffffffu, cs2, s);
        cs3 += __shfl_xor_sync(0xffffffffu, cs3, s);
    }
    if (lane < 4) {
        float* rp = &g_part[((b * MZ_) + mz) * HW_ + n0 + 16 * w];
        rp[2 * tq]     = cs0;
        rp[2 * tq + 1] = cs1;
        rp[2 * tq + 8] = cs2;
        rp[2 * tq + 9] = cs3;
    }
}

// ---------------- kernel 3: Vs^T = bf16(gamma * v / rowsum), rowsum reduced inline ----------------
__global__ void scalev_kernel(const float* __restrict__ gamma)
{
    size_t o = (size_t)blockIdx.x * 256 + threadIdx.x;  // over B*C*HW, n fastest
    int n = (int)(o % HW_);
    int c = (int)((o / HW_) % C_);
    int b = (int)(o / ((size_t)HW_ * C_));
    float s = 0.f;
    #pragma unroll
    for (int mz = 0; mz < MZ_; mz++)
        s += g_part[((b * MZ_) + mz) * HW_ + n];
    float val = g_v[((size_t)(b * HW_ + n)) * C_ + c] * gamma[0] / s;
    g_vsT[o] = __float2bfloat16(val);
}

// ---------------- kernel 4: fused P-in-registers GEMM + residual ----------------
// block = 64 m x 64 c, 128 threads (4 warps). Warp owns 32 m (wm=w&1) and every
// other n-chunk (wn=w>>1): each ldsm'd Vs fragment feeds 2 m-tiles; per-warp
// ldsm bytes and barrier count halved vs R10. Cross-parity acc reduce at end.
#define VSOFF   0
#define VSBUF   17408                    // 64 rows x 136 bf16
#define QSOFF   (4 * VSBUF)              // 69632
#define QSBUF   4096                     // 128 rows x 8 words
#define FK_SMEM (QSOFF + 4 * QSBUF)      // 86016

__global__ __launch_bounds__(128, 2)
void fused_kernel(const float* __restrict__ x, float* __restrict__ out)
{
    extern __shared__ __align__(16) char smem[];
    __nv_bfloat16* VsB = (__nv_bfloat16*)(smem + VSOFF);
    unsigned*      QsB = (unsigned*)(smem + QSOFF);
#define VS(bf, p, r, c) VsB[((bf) * 2 + (p)) * (64 * 136) + (r) * 136 + (c)]
#define QS(bf, p)       (QsB + ((bf) * 2 + (p)) * 1024)

    int b  = blockIdx.y;
    int m0 = blockIdx.x * 64;
    int t = threadIdx.x, lane = t & 31, w = t >> 5;     // 4 warps
    int g = lane >> 2, tq = lane & 3;
    int wm = w & 1;        // m-half (32 rows)
    int wn = w >> 1;       // n-chunk parity
    size_t bHW = (size_t)b * HW_;
    const unsigned* kb = &g_k[bHW * 8];
    const unsigned* qb = &g_q[bHW * 8];
    const __nv_bfloat16* Ag = &g_vsT[(size_t)b * C_ * HW_];

    // K A-fragments for this warp's 32 m-rows (2 m-tiles, fixed all kernel)
    int mw = m0 + 32 * wm;
    unsigned ka[2][4];
    #pragma unroll
    for (int mt = 0; mt < 2; mt++) {
        ka[mt][0] = kb[(mw + 16 * mt + g    ) * 8 + tq    ];
        ka[mt][1] = kb[(mw + 16 * mt + g + 8) * 8 + tq    ];
        ka[mt][2] = kb[(mw + 16 * mt + g    ) * 8 + tq + 4];
        ka[mt][3] = kb[(mw + 16 * mt + g + 8) * 8 + tq + 4];
    }

    float acc[2][8][4];
    #pragma unroll
    for (int mt = 0; mt < 2; mt++)
        #pragma unroll
        for (int i = 0; i < 8; i++)
            #pragma unroll
            for (int j = 0; j < 4; j++) acc[mt][i][j] = 0.f;

    // prefetch pair 0 (chunks 0 and 1)
    #pragma unroll
    for (int p = 0; p < 2; p++) {
        #pragma unroll
        for (int j = 0; j < 8; j++) {
            int idx = t + j * 128, row = idx >> 4, seg = idx & 15;
            cpa16(&VS(0, p, row, seg * 8), Ag + (size_t)row * HW_ + p * 128 + seg * 8);
        }
        #pragma unroll
        for (int j = 0; j < 2; j++) {
            int idx = t + j * 128, row = idx >> 1, seg = idx & 1;
            cpa16(QS(0, p) + row * 8 + seg * 4, qb + (size_t)(p * 128 + row) * 8 + seg * 4);
        }
    }
    cpa_commit();
    cpa_wait<0>();
    __syncthreads();

    for (int jp = 0; jp < NMT / 2; jp++) {
        int buf = jp & 1;
        bool more = (jp + 1 < NMT / 2);
        if (more) {
            int nbase = (jp + 1) * 256;
            #pragma unroll
            for (int p = 0; p < 2; p++) {
                #pragma unroll
                for (int j = 0; j < 8; j++) {
                    int idx = t + j * 128, row = idx >> 4, seg = idx & 15;
                    cpa16(&VS(buf ^ 1, p, row, seg * 8),
                          Ag + (size_t)row * HW_ + nbase + p * 128 + seg * 8);
                }
                #pragma unroll
                for (int j = 0; j < 2; j++) {
                    int idx = t + j * 128, row = idx >> 1, seg = idx & 1;
                    cpa16(QS(buf ^ 1, p) + row * 8 + seg * 4,
                          qb + (size_t)(nbase + p * 128 + row) * 8 + seg * 4);
                }
            }
            cpa_commit();
        }

        // consume chunk 2*jp + wn
        const unsigned* qs = QS(buf, wn);
        #pragma unroll
        for (int s = 0; s < 8; s++) {
            int nb = 16 * s;
            unsigned q0 = qs[(nb + g    ) * 8 + tq    ];
            unsigned q1 = qs[(nb + g    ) * 8 + tq + 4];
            unsigned q2 = qs[(nb + 8 + g) * 8 + tq    ];
            unsigned q3 = qs[(nb + 8 + g) * 8 + tq + 4];
            unsigned a[2][4];
            #pragma unroll
            for (int mt = 0; mt < 2; mt++) {
                float d[4] = {0.f, 0.f, 0.f, 0.f};
                float e[4] = {0.f, 0.f, 0.f, 0.f};
                mma_tf32(d, ka[mt], q0, q1);
                mma_tf32(e, ka[mt], q2, q3);
                a[mt][0] = packbf2(ex2(d[1]), ex2(d[0]));
                a[mt][1] = packbf2(ex2(d[3]), ex2(d[2]));
                a[mt][2] = packbf2(ex2(e[1]), ex2(e[0]));
                a[mt][3] = packbf2(ex2(e[3]), ex2(e[2]));
            }
            #pragma unroll
            for (int cb = 0; cb < 4; cb++) {
                unsigned bb[4];
                ldsm4(bb, &VS(buf, wn, cb * 16 + (lane & 7) + ((lane >> 4) & 1) * 8,
                              nb + ((lane >> 3) & 1) * 8));
                #pragma unroll
                for (int mt = 0; mt < 2; mt++) {
                    mma_bf16(acc[mt][2 * cb    ], a[mt], bb[0], bb[1]);
                    mma_bf16(acc[mt][2 * cb + 1], a[mt], bb[2], bb[3]);
                }
            }
        }
        if (more) cpa_wait<0>();
        __syncthreads();
    }

    // cross-parity reduction (reuse Vs smem area; conflict-free [idx][lane] layout)
    float* red = (float*)smem;
    if (wn == 1) {
        const float* af = (const float*)acc;
        #pragma unroll
        for (int i = 0; i < 64; i++) red[(wm * 64 + i) * 32 + lane] = af[i];
    }
    __syncthreads();
    if (wn == 0) {
        float* af = (float*)acc;
        #pragma unroll
        for (int i = 0; i < 64; i++) af[i] += red[(wm * 64 + i) * 32 + lane];

        // epilogue: out[b][m][c] = D[m][c] + x[b][m][c], 32 rows per warp
        #pragma unroll
        for (int mt = 0; mt < 2; mt++) {
            int m = m0 + 32 * wm + 16 * mt + g;
            #pragma unroll
            for (int o = 0; o < 8; o++) {
                int c = 8 * o + 2 * tq;
                size_t i0 = (bHW + m) * (size_t)C_ + c;
                size_t i1 = i0 + 8 * C_;
                float2 x0 = *(const float2*)&x[i0];
                float2 x1 = *(const float2*)&x[i1];
                float2 o0 = { acc[mt][o][0] + x0.x, acc[mt][o][1] + x0.y };
                float2 o1 = { acc[mt][o][2] + x1.x, acc[mt][o][3] + x1.y };
                *(float2*)&out[i0] = o0;
                *(float2*)&out[i1] = o1;
            }
        }
    }
#undef VS
#undef QS
}

// ---------------- launch ----------------
extern "C" void kernel_launch(void* const* d_in, const int* in_sizes, int n_in,
                              void* d_out, int out_size)
{
    const float* x     = (const float*)d_in[0];
    const float* Wq    = (const float*)d_in[1];
    const float* bq    = (const float*)d_in[2];
    const float* gq    = (const float*)d_in[3];
    const float* betaq = (const float*)d_in[4];
    const float* mq    = (const float*)d_in[5];
    const float* vq    = (const float*)d_in[6];
    const float* Wk    = (const float*)d_in[7];
    const float* bk    = (const float*)d_in[8];
    const float* gk    = (const float*)d_in[9];
    const float* betak = (const float*)d_in[10];
    const float* mk    = (const float*)d_in[11];
    const float* vk    = (const float*)d_in[12];
    const float* Wv    = (const float*)d_in[13];
    const float* bv    = (const float*)d_in[14];
    const float* gamma = (const float*)d_in[15];
    float* out = (float*)d_out;

    // unconditional, idempotent; host-side attribute set (not a stream op)
    cudaFuncSetAttribute(fused_kernel, cudaFuncAttributeMaxDynamicSharedMemorySize, FK_SMEM);

    prep_kernel<<<BHW / 4, 256>>>(x, Wq, bq, gq, betaq, mq, vq,
                                  Wk, bk, gk, betak, mk, vk, Wv, bv);
    stats_kernel<<<dim3(NMT, B_, MZ_), 256>>>();
    scalev_kernel<<<(unsigned)(((size_t)B_ * C_ * HW_) / 256), 256>>>(gamma);
    fused_kernel<<<dim3(HW_ / 64, B_), 128, FK_SMEM>>>(x, out);
}